// round 10
// baseline (speedup 1.0000x reference)
#include <cuda_runtime.h>
#include <math.h>
#include <stdint.h>

#define NN 50000
#define EE 800000
#define BN_EPS 1e-3f

// ---------------- device scratch (no allocation allowed) ----------------
// W fragment buffers: 10 K64-chunks of [64k x 128m], each 16384 floats
// (hi plane 8192 + lo plane 8192).
// chunks 0-1: prep0, 2-3: prep1, 4-7: upd0 (K=256), 8-9: upd1
__device__ float g_Wfrag[10 * 16384];
__device__ float g_bp0[128];
__device__ float g_bp1[128];
__device__ float g_bu0[128];
__device__ float g_bu1[128];

__device__ float g_bufA[NN * 128];   // intermediate activations
__device__ float g_prep[NN * 128];   // prep FFN output (per-node messages)
__device__ float g_agg[NN * 128];    // aggregated sums
__device__ float g_cnt[NN];          // per-node edge counts

// ---------------- helpers ----------------
__device__ __forceinline__ float tf32_rna(float x) {
    uint32_t u;
    asm("cvt.rna.tf32.f32 %0, %1;" : "=r"(u) : "f"(x));
    return __uint_as_float(u);
}
__device__ __forceinline__ float gelu_f(float x) {
    return 0.5f * x * (1.0f + erff(x * 0.70710678118654752f));
}
// D += A(16x8 tf32, row) * B(8x8 tf32, col)
__device__ __forceinline__ void mma_tf32(float* c, float4 a, float bx, float by) {
    asm("mma.sync.aligned.m16n8k8.row.col.f32.tf32.tf32.f32 "
        "{%0,%1,%2,%3},{%4,%5,%6,%7},{%8,%9},{%0,%1,%2,%3};"
        : "+f"(c[0]), "+f"(c[1]), "+f"(c[2]), "+f"(c[3])
        : "r"(__float_as_uint(a.x)), "r"(__float_as_uint(a.y)),
          "r"(__float_as_uint(a.z)), "r"(__float_as_uint(a.w)),
          "r"(__float_as_uint(bx)), "r"(__float_as_uint(by)));
}

// ---------------- fold W into tf32 hi/lo fragment planes (K64 chunks) ----------------
// Entry idx within chunk: idx = (ks*8 + mt)*32 + lane, ks,mt in 0..7.
// a0=(r0,k0) a1=(r1,k0) a2=(r0,k1) a3=(r1,k1);
// r0 = mt*16 + lane/4, r1 = r0+8, k0 = ks*8 + lane%4 (chunk-local), k1 = k0+4.
// hi plane at chunkbase + idx*4, lo plane at chunkbase + 8192 + idx*4.
__global__ void fold_frag(
    const float* __restrict__ W0, const float* __restrict__ g0, const float* __restrict__ v0,
    const float* __restrict__ W1, const float* __restrict__ g1, const float* __restrict__ v1,
    const float* __restrict__ W2, const float* __restrict__ g2, const float* __restrict__ v2,
    const float* __restrict__ W3, const float* __restrict__ g3, const float* __restrict__ v3) {
    int t = blockIdx.x * 256 + threadIdx.x;   // 0 .. 20479
    int chunk = t >> 11;                      // 0..9
    int idx = t & 2047;
    const float *W, *g, *v;
    int koff;
    if (chunk < 2)      { W = W0; g = g0; v = v0; koff = chunk * 64; }
    else if (chunk < 4) { W = W1; g = g1; v = v1; koff = (chunk - 2) * 64; }
    else if (chunk < 8) { W = W2; g = g2; v = v2; koff = (chunk - 4) * 64; }
    else                { W = W3; g = g3; v = v3; koff = (chunk - 8) * 64; }
    int lane = idx & 31;
    int mt = (idx >> 5) & 7;
    int ks = idx >> 8;                        // 0..7
    int r0 = mt * 16 + (lane >> 2);
    int r1 = r0 + 8;
    int kg0 = koff + ks * 8 + (lane & 3);
    int kg1 = kg0 + 4;
    float s0 = g[kg0] * rsqrtf(v[kg0] + BN_EPS);
    float s1 = g[kg1] * rsqrtf(v[kg1] + BN_EPS);
    float v00 = W[kg0 * 128 + r0] * s0;   // a0
    float v10 = W[kg0 * 128 + r1] * s0;   // a1
    float v01 = W[kg1 * 128 + r0] * s1;   // a2
    float v11 = W[kg1 * 128 + r1] * s1;   // a3
    float h00 = tf32_rna(v00), h10 = tf32_rna(v10), h01 = tf32_rna(v01), h11 = tf32_rna(v11);
    float l00 = tf32_rna(v00 - h00), l10 = tf32_rna(v10 - h10);
    float l01 = tf32_rna(v01 - h01), l11 = tf32_rna(v11 - h11);
    float* base = g_Wfrag + chunk * 16384;
    *reinterpret_cast<float4*>(base + idx * 4)        = make_float4(h00, h10, h01, h11);
    *reinterpret_cast<float4*>(base + 8192 + idx * 4) = make_float4(l00, l10, l01, l11);
}

// b'[j] = bias[j] + sum_i (b_i - m_i*s_i) * W[i][j]
__global__ void fold_b_all(
    const float* __restrict__ g0, const float* __restrict__ b0, const float* __restrict__ m0, const float* __restrict__ v0, const float* __restrict__ W0, const float* __restrict__ s0, float* __restrict__ o0,
    const float* __restrict__ g1, const float* __restrict__ b1, const float* __restrict__ m1, const float* __restrict__ v1, const float* __restrict__ W1, const float* __restrict__ s1, float* __restrict__ o1,
    const float* __restrict__ g2, const float* __restrict__ b2, const float* __restrict__ m2, const float* __restrict__ v2, const float* __restrict__ W2, const float* __restrict__ s2, float* __restrict__ o2,
    const float* __restrict__ g3, const float* __restrict__ b3, const float* __restrict__ m3, const float* __restrict__ v3, const float* __restrict__ W3, const float* __restrict__ s3, float* __restrict__ o3) {
    int l = blockIdx.x;
    const float *g, *b, *m, *v, *W, *s;
    float* o;
    int K;
    switch (l) {
        case 0:  g = g0; b = b0; m = m0; v = v0; W = W0; s = s0; o = o0; K = 128; break;
        case 1:  g = g1; b = b1; m = m1; v = v1; W = W1; s = s1; o = o1; K = 128; break;
        case 2:  g = g2; b = b2; m = m2; v = v2; W = W2; s = s2; o = o2; K = 256; break;
        default: g = g3; b = b3; m = m3; v = v3; W = W3; s = s3; o = o3; K = 128; break;
    }
    int j = threadIdx.x;
    float acc0 = s[j], acc1 = 0.f;
    #pragma unroll 8
    for (int i = 0; i < K; i += 2) {
        float sc0 = g[i] * rsqrtf(v[i] + BN_EPS);
        float sc1 = g[i + 1] * rsqrtf(v[i + 1] + BN_EPS);
        acc0 = fmaf(b[i] - m[i] * sc0, W[i * 128 + j], acc0);
        acc1 = fmaf(b[i + 1] - m[i + 1] * sc1, W[(i + 1) * 128 + j], acc1);
    }
    o[j] = acc0 + acc1;
}

// ---------------- zero agg + cnt ----------------
__global__ void zero_kernel() {
    int i = blockIdx.x * 256 + threadIdx.x;
    float4 z = make_float4(0.f, 0.f, 0.f, 0.f);
    if (i < NN * 128 / 4) reinterpret_cast<float4*>(g_agg)[i] = z;
    if (i < NN / 4)       reinterpret_cast<float4*>(g_cnt)[i] = z;
}

// ---------------- tensor-core GEMM + bias + gelu (2xTF32: split-W, single-B) --------
// Y[nrows,128] = gelu(X @ W' + b'), K in 64-wide chunks.
// Block: 256 threads, tile = 128 x-rows (N) x 128 w-cols (M). smem 96KB -> 2 blocks/SM.
// W hi/lo frags copied chunk-wise into smem (pre-folded in gmem, coalesced).
// x fragments: repack threads load DIRECTLY from gmem (warp covers 8 rows x 32B full
// sectors), single cvt.rna each, STS.64 into xf. No staging buffer, one sync saved.
// Mainloop: per (mt,nt): 2 MMAs (Ah*B + Al*B). W truncation fully compensated;
// x carries one rna rounding (~1.4e-4 per layer, well under 1e-3).
template <int CHUNKS, bool CONCAT>
__global__ void __launch_bounds__(256, 2)
gemm_tc(const float* __restrict__ X0, const float* __restrict__ Wfrag,
        const float* __restrict__ B, float* __restrict__ Y, int nrows) {
    extern __shared__ float sm[];
    float* ws = sm;                      // 16384 floats: W frag chunk (hi 8192 | lo 8192)
    float* xf = sm + 16384;              // 8192 floats: 4096 B-frag float2 {b0,b1}

    const int tid = threadIdx.x;
    const int lane = tid & 31;
    const int wid = tid >> 5;
    const int mg = wid & 3;              // M group (w-cols)
    const int ng = wid >> 2;             // N group (x-rows)
    const int row0 = blockIdx.x * 128;

    float c[2][8][4];
    #pragma unroll
    for (int mt = 0; mt < 2; mt++)
        #pragma unroll
        for (int nt = 0; nt < 8; nt++)
            #pragma unroll
            for (int j = 0; j < 4; j++) c[mt][nt][j] = 0.f;

    for (int cc = 0; cc < CHUNKS; cc++) {
        if (cc) __syncthreads();
        // ---- bulk-copy W frag chunk into smem (coalesced, fragment-ordered) ----
        {
            const float4* Wg = reinterpret_cast<const float4*>(Wfrag + cc * 16384);
            float4* Ws4 = reinterpret_cast<float4*>(ws);
            #pragma unroll
            for (int i = tid; i < 4096; i += 256) Ws4[i] = Wg[i];
        }
        // ---- x fragments straight from gmem: transpose + single tf32 rounding ----
        // entry e: le = e&31, nt = (e>>5)&15, ks = e>>9 (0..7)
        // b0 = x[nt*8 + le/4][koff + ks*8 + le%4], b1 = same col+4
        {
            const bool second = CONCAT && (cc >= CHUNKS / 2);
            const float* Xc = second ? g_agg : X0;
            const int koff = (CONCAT ? (cc % (CHUNKS / 2)) : cc) * 64;
            #pragma unroll
            for (int e = tid; e < 4096; e += 256) {
                int le = e & 31, nt = (e >> 5) & 15, ks = e >> 9;
                int row = row0 + nt * 8 + (le >> 2);
                int col = koff + ks * 8 + (le & 3);
                float v0 = 0.f, v1 = 0.f;
                if (row < nrows) {
                    const float* p = Xc + (size_t)row * 128 + col;
                    v0 = __ldg(p);
                    v1 = __ldg(p + 4);
                    if (second) {
                        float cn = g_cnt[row];
                        float f = (cn > 0.f) ? (1.0f / cn) : 0.f;
                        v0 *= f; v1 *= f;
                    }
                }
                *reinterpret_cast<float2*>(xf + e * 2) =
                    make_float2(tf32_rna(v0), tf32_rna(v1));
            }
        }
        __syncthreads();

        // ---- mainloop: 8 k-steps, A and B from smem, 2 MMAs per tile ----
        #pragma unroll
        for (int ks = 0; ks < 8; ks++) {
            float4 ah[2], al[2];
            #pragma unroll
            for (int mt = 0; mt < 2; mt++) {
                int aidx = (ks * 8 + mg * 2 + mt) * 32 + lane;
                ah[mt] = *reinterpret_cast<const float4*>(ws + aidx * 4);
                al[mt] = *reinterpret_cast<const float4*>(ws + 8192 + aidx * 4);
            }
            #pragma unroll
            for (int nt = 0; nt < 8; nt++) {
                float2 b = *reinterpret_cast<const float2*>(
                    xf + ((ks * 16 + ng * 8 + nt) * 32 + lane) * 2);
                #pragma unroll
                for (int mt = 0; mt < 2; mt++) {
                    mma_tf32(c[mt][nt], ah[mt], b.x, b.y);  // Ah * B
                    mma_tf32(c[mt][nt], al[mt], b.x, b.y);  // Al * B
                }
            }
        }
    }

    // ---- epilogue: bias + gelu + transposed store ----
    #pragma unroll
    for (int mt = 0; mt < 2; mt++) {
        int col0 = mg * 32 + mt * 16 + (lane >> 2);
        float bb0 = B[col0];
        float bb8 = B[col0 + 8];
        #pragma unroll
        for (int nt = 0; nt < 8; nt++) {
            int rowx = row0 + ng * 64 + nt * 8 + 2 * (lane & 3);
            if (rowx < nrows) {
                Y[(size_t)rowx * 128 + col0]     = gelu_f(c[mt][nt][0] + bb0);
                Y[(size_t)rowx * 128 + col0 + 8] = gelu_f(c[mt][nt][2] + bb8);
            }
            if (rowx + 1 < nrows) {
                Y[(size_t)(rowx + 1) * 128 + col0]     = gelu_f(c[mt][nt][1] + bb0);
                Y[(size_t)(rowx + 1) * 128 + col0 + 8] = gelu_f(c[mt][nt][3] + bb8);
            }
        }
    }
}

// ---------------- edge scatter: 4 edges per warp, loads batched for MLP ----------------
__global__ void __launch_bounds__(256)
scatter_kernel(const int* __restrict__ edges, const float* __restrict__ ew) {
    int warp = blockIdx.x * 8 + (threadIdx.x >> 5);
    int lane = threadIdx.x & 31;
    int e0 = warp * 4;

    int dst[4], src[4];
    float w[4];
    #pragma unroll
    for (int t = 0; t < 4; t++) {
        dst[t] = __ldg(edges + e0 + t);
        src[t] = __ldg(edges + EE + e0 + t);
        w[t]   = __ldg(ew + e0 + t);
    }
    float4 v[4];
    #pragma unroll
    for (int t = 0; t < 4; t++)
        v[t] = __ldg(reinterpret_cast<const float4*>(g_prep + (size_t)src[t] * 128) + lane);
    #pragma unroll
    for (int t = 0; t < 4; t++) {
        v[t].x *= w[t]; v[t].y *= w[t]; v[t].z *= w[t]; v[t].w *= w[t];
        float* dp = g_agg + (size_t)dst[t] * 128 + lane * 4;
        asm volatile("red.global.add.v4.f32 [%0], {%1, %2, %3, %4};"
                     :: "l"(dp), "f"(v[t].x), "f"(v[t].y), "f"(v[t].z), "f"(v[t].w) : "memory");
    }
    if (lane < 4) {
        asm volatile("red.global.add.f32 [%0], %1;"
                     :: "l"(g_cnt + dst[lane]), "f"(1.0f) : "memory");
    }
}

// ---------------- launch ----------------
extern "C" void kernel_launch(void* const* d_in, const int* in_sizes, int n_in,
                              void* d_out, int out_size) {
    const float* node_repr = (const float*)d_in[0];
    const int*   edges     = (const int*)d_in[1];
    const float* edge_w    = (const float*)d_in[2];

    const float* p0g = (const float*)d_in[3];  const float* p0b = (const float*)d_in[4];
    const float* p0m = (const float*)d_in[5];  const float* p0v = (const float*)d_in[6];
    const float* p0W = (const float*)d_in[7];  const float* p0bias = (const float*)d_in[8];
    const float* p1g = (const float*)d_in[9];  const float* p1b = (const float*)d_in[10];
    const float* p1m = (const float*)d_in[11]; const float* p1v = (const float*)d_in[12];
    const float* p1W = (const float*)d_in[13]; const float* p1bias = (const float*)d_in[14];
    const float* u0g = (const float*)d_in[15]; const float* u0b = (const float*)d_in[16];
    const float* u0m = (const float*)d_in[17]; const float* u0v = (const float*)d_in[18];
    const float* u0W = (const float*)d_in[19]; const float* u0bias = (const float*)d_in[20];
    const float* u1g = (const float*)d_in[21]; const float* u1b = (const float*)d_in[22];
    const float* u1m = (const float*)d_in[23]; const float* u1v = (const float*)d_in[24];
    const float* u1W = (const float*)d_in[25]; const float* u1bias = (const float*)d_in[26];

    float *pWfrag, *pbp0, *pbp1, *pbu0, *pbu1, *pBufA, *pPrep;
    cudaGetSymbolAddress((void**)&pWfrag, g_Wfrag);
    cudaGetSymbolAddress((void**)&pbp0, g_bp0);
    cudaGetSymbolAddress((void**)&pbp1, g_bp1);
    cudaGetSymbolAddress((void**)&pbu0, g_bu0);
    cudaGetSymbolAddress((void**)&pbu1, g_bu1);
    cudaGetSymbolAddress((void**)&pBufA, g_bufA);
    cudaGetSymbolAddress((void**)&pPrep, g_prep);

    const int smemB = (16384 + 8192) * 4;   // 98304 B -> 2 blocks/SM
    cudaFuncSetAttribute(gemm_tc<2, false>, cudaFuncAttributeMaxDynamicSharedMemorySize, smemB);
    cudaFuncSetAttribute(gemm_tc<4, true>,  cudaFuncAttributeMaxDynamicSharedMemorySize, smemB);

    // 1) fold BN + tf32 hi/lo split into K64-chunk fragment planes, fold biases
    fold_frag<<<80, 256>>>(p0W, p0g, p0v,
                           p1W, p1g, p1v,
                           u0W, u0g, u0v,
                           u1W, u1g, u1v);
    fold_b_all<<<4, 128>>>(p0g, p0b, p0m, p0v, p0W, p0bias, pbp0,
                           p1g, p1b, p1m, p1v, p1W, p1bias, pbp1,
                           u0g, u0b, u0m, u0v, u0W, u0bias, pbu0,
                           u1g, u1b, u1m, u1v, u1W, u1bias, pbu1);

    // 2) zero aggregation buffers
    zero_kernel<<<(NN * 128 / 4 + 255) / 256, 256>>>();

    const int gblocks = (NN + 127) / 128;  // 391
    // 3) prepare FFN per NODE (16x algebraic reduction vs per-edge)
    gemm_tc<2, false><<<gblocks, 256, smemB>>>(node_repr, pWfrag,             pbp0, pBufA, NN);
    gemm_tc<2, false><<<gblocks, 256, smemB>>>(pBufA,     pWfrag + 2 * 16384, pbp1, pPrep, NN);

    // 4) scatter-aggregate along edges
    scatter_kernel<<<EE / 32, 256>>>(edges, edge_w);

    // 5) update FFN: concat(node_repr, agg_mean) -> H, then H -> H (writes d_out)
    gemm_tc<4, true><<<gblocks, 256, smemB>>>(node_repr, pWfrag + 4 * 16384, pbu0, pBufA, NN);
    gemm_tc<2, false><<<gblocks, 256, smemB>>>(pBufA,    pWfrag + 8 * 16384, pbu1, (float*)d_out, NN);
}

// round 12
// speedup vs baseline: 1.0361x; 1.0361x over previous
#include <cuda_runtime.h>
#include <math.h>
#include <stdint.h>

#define NN 50000
#define EE 800000
#define BN_EPS 1e-3f

// ---------------- device scratch (no allocation allowed) ----------------
// W fragment buffers: 20 K32-chunks of [32k x 128m], each 8192 floats
// (hi plane 4096 + lo plane 4096).
// chunks 0-3: prep0, 4-7: prep1, 8-15: upd0 (K=256), 16-19: upd1
__device__ float g_Wfrag[20 * 8192];
__device__ float g_bp0[128];
__device__ float g_bp1[128];
__device__ float g_bu0[128];
__device__ float g_bu1[128];

__device__ float g_bufA[NN * 128];   // intermediate activations
__device__ float g_prep[NN * 128];   // prep FFN output (per-node messages)
__device__ float g_agg[NN * 128];    // aggregated sums
__device__ float g_cnt[NN];          // per-node edge counts

// ---------------- helpers ----------------
__device__ __forceinline__ float tf32_rna(float x) {
    uint32_t u;
    asm("cvt.rna.tf32.f32 %0, %1;" : "=r"(u) : "f"(x));
    return __uint_as_float(u);
}
__device__ __forceinline__ float gelu_f(float x) {
    return 0.5f * x * (1.0f + erff(x * 0.70710678118654752f));
}
// D += A(16x8 tf32, row) * B(8x8 tf32, col)
__device__ __forceinline__ void mma_tf32(float* c, float4 a, float bx, float by) {
    asm("mma.sync.aligned.m16n8k8.row.col.f32.tf32.tf32.f32 "
        "{%0,%1,%2,%3},{%4,%5,%6,%7},{%8,%9},{%0,%1,%2,%3};"
        : "+f"(c[0]), "+f"(c[1]), "+f"(c[2]), "+f"(c[3])
        : "r"(__float_as_uint(a.x)), "r"(__float_as_uint(a.y)),
          "r"(__float_as_uint(a.z)), "r"(__float_as_uint(a.w)),
          "r"(__float_as_uint(bx)), "r"(__float_as_uint(by)));
}

// ---------------- fold W into tf32 hi/lo fragment planes (K32 chunks) ----------------
// Entry idx within chunk: idx = (ks*8 + mt)*32 + lane, ks in 0..3, mt in 0..7.
// a0=(r0,k0) a1=(r1,k0) a2=(r0,k1) a3=(r1,k1);
// r0 = mt*16 + lane/4, r1 = r0+8, k0 = ks*8 + lane%4 (chunk-local), k1 = k0+4.
// hi plane at chunkbase + idx*4, lo plane at chunkbase + 4096 + idx*4.
__global__ void fold_frag(
    const float* __restrict__ W0, const float* __restrict__ g0, const float* __restrict__ v0,
    const float* __restrict__ W1, const float* __restrict__ g1, const float* __restrict__ v1,
    const float* __restrict__ W2, const float* __restrict__ g2, const float* __restrict__ v2,
    const float* __restrict__ W3, const float* __restrict__ g3, const float* __restrict__ v3) {
    int t = blockIdx.x * 256 + threadIdx.x;   // 0 .. 20479
    int chunk = t >> 10;                      // 0..19
    int idx = t & 1023;
    const float *W, *g, *v;
    int koff;
    if (chunk < 4)       { W = W0; g = g0; v = v0; koff = chunk * 32; }
    else if (chunk < 8)  { W = W1; g = g1; v = v1; koff = (chunk - 4) * 32; }
    else if (chunk < 16) { W = W2; g = g2; v = v2; koff = (chunk - 8) * 32; }
    else                 { W = W3; g = g3; v = v3; koff = (chunk - 16) * 32; }
    int lane = idx & 31;
    int mt = (idx >> 5) & 7;
    int ks = idx >> 8;                        // 0..3
    int r0 = mt * 16 + (lane >> 2);
    int r1 = r0 + 8;
    int kg0 = koff + ks * 8 + (lane & 3);
    int kg1 = kg0 + 4;
    float s0 = g[kg0] * rsqrtf(v[kg0] + BN_EPS);
    float s1 = g[kg1] * rsqrtf(v[kg1] + BN_EPS);
    float v00 = W[kg0 * 128 + r0] * s0;   // a0
    float v10 = W[kg0 * 128 + r1] * s0;   // a1
    float v01 = W[kg1 * 128 + r0] * s1;   // a2
    float v11 = W[kg1 * 128 + r1] * s1;   // a3
    float h00 = tf32_rna(v00), h10 = tf32_rna(v10), h01 = tf32_rna(v01), h11 = tf32_rna(v11);
    float l00 = tf32_rna(v00 - h00), l10 = tf32_rna(v10 - h10);
    float l01 = tf32_rna(v01 - h01), l11 = tf32_rna(v11 - h11);
    float* base = g_Wfrag + chunk * 8192;
    *reinterpret_cast<float4*>(base + idx * 4)        = make_float4(h00, h10, h01, h11);
    *reinterpret_cast<float4*>(base + 4096 + idx * 4) = make_float4(l00, l10, l01, l11);
}

// b'[j] = bias[j] + sum_i (b_i - m_i*s_i) * W[i][j]
__global__ void fold_b_all(
    const float* __restrict__ g0, const float* __restrict__ b0, const float* __restrict__ m0, const float* __restrict__ v0, const float* __restrict__ W0, const float* __restrict__ s0, float* __restrict__ o0,
    const float* __restrict__ g1, const float* __restrict__ b1, const float* __restrict__ m1, const float* __restrict__ v1, const float* __restrict__ W1, const float* __restrict__ s1, float* __restrict__ o1,
    const float* __restrict__ g2, const float* __restrict__ b2, const float* __restrict__ m2, const float* __restrict__ v2, const float* __restrict__ W2, const float* __restrict__ s2, float* __restrict__ o2,
    const float* __restrict__ g3, const float* __restrict__ b3, const float* __restrict__ m3, const float* __restrict__ v3, const float* __restrict__ W3, const float* __restrict__ s3, float* __restrict__ o3) {
    int l = blockIdx.x;
    const float *g, *b, *m, *v, *W, *s;
    float* o;
    int K;
    switch (l) {
        case 0:  g = g0; b = b0; m = m0; v = v0; W = W0; s = s0; o = o0; K = 128; break;
        case 1:  g = g1; b = b1; m = m1; v = v1; W = W1; s = s1; o = o1; K = 128; break;
        case 2:  g = g2; b = b2; m = m2; v = v2; W = W2; s = s2; o = o2; K = 256; break;
        default: g = g3; b = b3; m = m3; v = v3; W = W3; s = s3; o = o3; K = 128; break;
    }
    int j = threadIdx.x;
    float acc0 = s[j], acc1 = 0.f;
    #pragma unroll 8
    for (int i = 0; i < K; i += 2) {
        float sc0 = g[i] * rsqrtf(v[i] + BN_EPS);
        float sc1 = g[i + 1] * rsqrtf(v[i + 1] + BN_EPS);
        acc0 = fmaf(b[i] - m[i] * sc0, W[i * 128 + j], acc0);
        acc1 = fmaf(b[i + 1] - m[i + 1] * sc1, W[(i + 1) * 128 + j], acc1);
    }
    o[j] = acc0 + acc1;
}

// ---------------- zero agg + cnt ----------------
__global__ void zero_kernel() {
    int i = blockIdx.x * 256 + threadIdx.x;
    float4 z = make_float4(0.f, 0.f, 0.f, 0.f);
    if (i < NN * 128 / 4) reinterpret_cast<float4*>(g_agg)[i] = z;
    if (i < NN / 4)       reinterpret_cast<float4*>(g_cnt)[i] = z;
}

// ---------------- tensor-core GEMM + bias + gelu (3xTF32, 64-row tiles, 3 blk/SM) ----
// Y[nrows,128] = gelu(X @ W' + b'), K in 32-wide chunks.
// Block: 256 threads, tile = 64 x-rows (N) x 128 w-cols (M). smem 48KB -> 3 blocks/SM,
// 6 warps/SMSP: staging phases of one block overlap mainloops of the other two.
// Warps: mg = wid&3 (M stripe of 32 = 2 m-tiles), ng = wid>>2 in 0..1 (N stripe of 32
// = 4 n-tiles). x fragments loaded DIRECTLY from gmem (L2-hot) with hi/lo tf32 split.
template <int CHUNKS, bool CONCAT>
__global__ void __launch_bounds__(256, 3)
gemm_tc(const float* __restrict__ X0, const float* __restrict__ Wfrag,
        const float* __restrict__ B, float* __restrict__ Y, int nrows) {
    extern __shared__ float sm[];
    float* ws = sm;                      // 8192 floats: W frag chunk (hi 4096 | lo 4096)
    float* xf = sm + 8192;               // 4096 floats: 1024 B-frag float4 {b0h,b1h,b0l,b1l}

    const int tid = threadIdx.x;
    const int lane = tid & 31;
    const int wid = tid >> 5;
    const int mg = wid & 3;              // M group (w-cols)
    const int ng = wid >> 2;             // N group (x-rows), 0..1
    const int row0 = blockIdx.x * 64;

    float c[2][4][4];
    #pragma unroll
    for (int mt = 0; mt < 2; mt++)
        #pragma unroll
        for (int nt = 0; nt < 4; nt++)
            #pragma unroll
            for (int j = 0; j < 4; j++) c[mt][nt][j] = 0.f;

    for (int cc = 0; cc < CHUNKS; cc++) {
        if (cc) __syncthreads();
        // ---- bulk-copy W frag chunk into smem (coalesced, fragment-ordered) ----
        {
            const float4* Wg = reinterpret_cast<const float4*>(Wfrag + cc * 8192);
            float4* Ws4 = reinterpret_cast<float4*>(ws);
            #pragma unroll
            for (int i = tid; i < 2048; i += 256) Ws4[i] = Wg[i];
        }
        // ---- x fragments straight from gmem: transpose + tf32 hi/lo split ----
        // entry e: le = e&31, ntg = (e>>5)&7 (global n-tile), ks = e>>8 (0..3)
        // b0 = x[ntg*8 + le/4][koff + ks*8 + le%4], b1 = same col+4
        {
            const bool second = CONCAT && (cc >= CHUNKS / 2);
            const float* Xc = second ? g_agg : X0;
            const int koff = (CONCAT ? (cc % (CHUNKS / 2)) : cc) * 32;
            #pragma unroll
            for (int e = tid; e < 1024; e += 256) {
                int le = e & 31, ntg = (e >> 5) & 7, ks = e >> 8;
                int row = row0 + ntg * 8 + (le >> 2);
                int col = koff + ks * 8 + (le & 3);
                float v0 = 0.f, v1 = 0.f;
                if (row < nrows) {
                    const float* p = Xc + (size_t)row * 128 + col;
                    v0 = __ldg(p);
                    v1 = __ldg(p + 4);
                    if (second) {
                        float cn = g_cnt[row];
                        float f = (cn > 0.f) ? (1.0f / cn) : 0.f;
                        v0 *= f; v1 *= f;
                    }
                }
                float h0 = tf32_rna(v0), h1 = tf32_rna(v1);
                float l0 = tf32_rna(v0 - h0), l1 = tf32_rna(v1 - h1);
                *reinterpret_cast<float4*>(xf + e * 4) = make_float4(h0, h1, l0, l1);
            }
        }
        __syncthreads();

        // ---- mainloop: 4 k-steps, A and B from smem, 3 MMAs per tile (3xTF32) ----
        #pragma unroll
        for (int ks = 0; ks < 4; ks++) {
            float4 ah[2], al[2];
            #pragma unroll
            for (int mt = 0; mt < 2; mt++) {
                int aidx = (ks * 8 + mg * 2 + mt) * 32 + lane;
                ah[mt] = *reinterpret_cast<const float4*>(ws + aidx * 4);
                al[mt] = *reinterpret_cast<const float4*>(ws + 4096 + aidx * 4);
            }
            #pragma unroll
            for (int nt = 0; nt < 4; nt++) {
                float4 b = *reinterpret_cast<const float4*>(
                    xf + ((ks * 8 + ng * 4 + nt) * 32 + lane) * 4);
                #pragma unroll
                for (int mt = 0; mt < 2; mt++) {
                    mma_tf32(c[mt][nt], ah[mt], b.x, b.y);  // Ah * Bh
                    mma_tf32(c[mt][nt], ah[mt], b.z, b.w);  // Ah * Bl
                    mma_tf32(c[mt][nt], al[mt], b.x, b.y);  // Al * Bh
                }
            }
        }
    }

    // ---- epilogue: bias + gelu + transposed store ----
    #pragma unroll
    for (int mt = 0; mt < 2; mt++) {
        int col0 = mg * 32 + mt * 16 + (lane >> 2);
        float bb0 = B[col0];
        float bb8 = B[col0 + 8];
        #pragma unroll
        for (int nt = 0; nt < 4; nt++) {
            int rowx = row0 + (ng * 4 + nt) * 8 + 2 * (lane & 3);
            if (rowx < nrows) {
                Y[(size_t)rowx * 128 + col0]     = gelu_f(c[mt][nt][0] + bb0);
                Y[(size_t)rowx * 128 + col0 + 8] = gelu_f(c[mt][nt][2] + bb8);
            }
            if (rowx + 1 < nrows) {
                Y[(size_t)(rowx + 1) * 128 + col0]     = gelu_f(c[mt][nt][1] + bb0);
                Y[(size_t)(rowx + 1) * 128 + col0 + 8] = gelu_f(c[mt][nt][3] + bb8);
            }
        }
    }
}

// ---------------- edge scatter: 4 edges per warp, loads batched for MLP ----------------
__global__ void __launch_bounds__(256)
scatter_kernel(const int* __restrict__ edges, const float* __restrict__ ew) {
    int warp = blockIdx.x * 8 + (threadIdx.x >> 5);
    int lane = threadIdx.x & 31;
    int e0 = warp * 4;

    int dst[4], src[4];
    float w[4];
    #pragma unroll
    for (int t = 0; t < 4; t++) {
        dst[t] = __ldg(edges + e0 + t);
        src[t] = __ldg(edges + EE + e0 + t);
        w[t]   = __ldg(ew + e0 + t);
    }
    float4 v[4];
    #pragma unroll
    for (int t = 0; t < 4; t++)
        v[t] = __ldg(reinterpret_cast<const float4*>(g_prep + (size_t)src[t] * 128) + lane);
    #pragma unroll
    for (int t = 0; t < 4; t++) {
        v[t].x *= w[t]; v[t].y *= w[t]; v[t].z *= w[t]; v[t].w *= w[t];
        float* dp = g_agg + (size_t)dst[t] * 128 + lane * 4;
        asm volatile("red.global.add.v4.f32 [%0], {%1, %2, %3, %4};"
                     :: "l"(dp), "f"(v[t].x), "f"(v[t].y), "f"(v[t].z), "f"(v[t].w) : "memory");
    }
    if (lane < 4) {
        asm volatile("red.global.add.f32 [%0], %1;"
                     :: "l"(g_cnt + dst[lane]), "f"(1.0f) : "memory");
    }
}

// ---------------- launch ----------------
extern "C" void kernel_launch(void* const* d_in, const int* in_sizes, int n_in,
                              void* d_out, int out_size) {
    const float* node_repr = (const float*)d_in[0];
    const int*   edges     = (const int*)d_in[1];
    const float* edge_w    = (const float*)d_in[2];

    const float* p0g = (const float*)d_in[3];  const float* p0b = (const float*)d_in[4];
    const float* p0m = (const float*)d_in[5];  const float* p0v = (const float*)d_in[6];
    const float* p0W = (const float*)d_in[7];  const float* p0bias = (const float*)d_in[8];
    const float* p1g = (const float*)d_in[9];  const float* p1b = (const float*)d_in[10];
    const float* p1m = (const float*)d_in[11]; const float* p1v = (const float*)d_in[12];
    const float* p1W = (const float*)d_in[13]; const float* p1bias = (const float*)d_in[14];
    const float* u0g = (const float*)d_in[15]; const float* u0b = (const float*)d_in[16];
    const float* u0m = (const float*)d_in[17]; const float* u0v = (const float*)d_in[18];
    const float* u0W = (const float*)d_in[19]; const float* u0bias = (const float*)d_in[20];
    const float* u1g = (const float*)d_in[21]; const float* u1b = (const float*)d_in[22];
    const float* u1m = (const float*)d_in[23]; const float* u1v = (const float*)d_in[24];
    const float* u1W = (const float*)d_in[25]; const float* u1bias = (const float*)d_in[26];

    float *pWfrag, *pbp0, *pbp1, *pbu0, *pbu1, *pBufA, *pPrep;
    cudaGetSymbolAddress((void**)&pWfrag, g_Wfrag);
    cudaGetSymbolAddress((void**)&pbp0, g_bp0);
    cudaGetSymbolAddress((void**)&pbp1, g_bp1);
    cudaGetSymbolAddress((void**)&pbu0, g_bu0);
    cudaGetSymbolAddress((void**)&pbu1, g_bu1);
    cudaGetSymbolAddress((void**)&pBufA, g_bufA);
    cudaGetSymbolAddress((void**)&pPrep, g_prep);

    const int smemB = (8192 + 4096) * 4;   // 49152 B -> 3 blocks/SM
    cudaFuncSetAttribute(gemm_tc<4, false>, cudaFuncAttributeMaxDynamicSharedMemorySize, smemB);
    cudaFuncSetAttribute(gemm_tc<8, true>,  cudaFuncAttributeMaxDynamicSharedMemorySize, smemB);

    // 1) fold BN + tf32 hi/lo split into K32-chunk fragment planes, fold biases
    fold_frag<<<80, 256>>>(p0W, p0g, p0v,
                           p1W, p1g, p1v,
                           u0W, u0g, u0v,
                           u1W, u1g, u1v);
    fold_b_all<<<4, 128>>>(p0g, p0b, p0m, p0v, p0W, p0bias, pbp0,
                           p1g, p1b, p1m, p1v, p1W, p1bias, pbp1,
                           u0g, u0b, u0m, u0v, u0W, u0bias, pbu0,
                           u1g, u1b, u1m, u1v, u1W, u1bias, pbu1);

    // 2) zero aggregation buffers
    zero_kernel<<<(NN * 128 / 4 + 255) / 256, 256>>>();

    const int gblocks = (NN + 63) / 64;  // 782
    // 3) prepare FFN per NODE (16x algebraic reduction vs per-edge)
    gemm_tc<4, false><<<gblocks, 256, smemB>>>(node_repr, pWfrag,             pbp0, pBufA, NN);
    gemm_tc<4, false><<<gblocks, 256, smemB>>>(pBufA,     pWfrag + 4 * 8192,  pbp1, pPrep, NN);

    // 4) scatter-aggregate along edges
    scatter_kernel<<<EE / 32, 256>>>(edges, edge_w);

    // 5) update FFN: concat(node_repr, agg_mean) -> H, then H -> H (writes d_out)
    gemm_tc<8, true><<<gblocks, 256, smemB>>>(node_repr, pWfrag + 8 * 8192,   pbu0, pBufA, NN);
    gemm_tc<4, false><<<gblocks, 256, smemB>>>(pBufA,    pWfrag + 16 * 8192,  pbu1, (float*)d_out, NN);
}

// round 13
// speedup vs baseline: 1.0921x; 1.0541x over previous
#include <cuda_runtime.h>
#include <math.h>
#include <stdint.h>

#define NN 50000
#define EE 800000
#define BN_EPS 1e-3f
#define NPAD 50304

// ---------------- device scratch (no allocation allowed) ----------------
// W fragment buffers: 20 K32-chunks of [32k x 128m], each 8192 floats
// (hi plane 4096 + lo plane 4096).
// chunks 0-3: prep0, 4-7: prep1, 8-15: upd0 (K=256), 16-19: upd1
__device__ float g_Wfrag[20 * 8192];
__device__ float g_bp0[128];
__device__ float g_bp1[128];
__device__ float g_bu0[128];
__device__ float g_bu1[128];

__device__ float g_bufA[NN * 128];       // intermediate activations
__device__ float g_prep[NN * 128];       // prep FFN output (per-node messages)
__device__ float g_agg[NN * 128];        // aggregated MEAN (pre-divided)

// CSR scratch
__device__ uint32_t g_cntU[NPAD];        // per-node edge counts
__device__ uint32_t g_rowstart[NPAD];    // exclusive prefix of counts
__device__ uint32_t g_cursor[NPAD];      // fill cursors
__device__ uint32_t g_partials[256];     // block partial sums for scan
__device__ int      g_csrSrc[EE];        // src node per CSR slot
__device__ float    g_csrW[EE];          // edge weight per CSR slot

// ---------------- helpers ----------------
__device__ __forceinline__ float tf32_rna(float x) {
    uint32_t u;
    asm("cvt.rna.tf32.f32 %0, %1;" : "=r"(u) : "f"(x));
    return __uint_as_float(u);
}
__device__ __forceinline__ float gelu_f(float x) {
    return 0.5f * x * (1.0f + erff(x * 0.70710678118654752f));
}
// D += A(16x8 tf32, row) * B(8x8 tf32, col)
__device__ __forceinline__ void mma_tf32(float* c, float4 a, float bx, float by) {
    asm("mma.sync.aligned.m16n8k8.row.col.f32.tf32.tf32.f32 "
        "{%0,%1,%2,%3},{%4,%5,%6,%7},{%8,%9},{%0,%1,%2,%3};"
        : "+f"(c[0]), "+f"(c[1]), "+f"(c[2]), "+f"(c[3])
        : "r"(__float_as_uint(a.x)), "r"(__float_as_uint(a.y)),
          "r"(__float_as_uint(a.z)), "r"(__float_as_uint(a.w)),
          "r"(__float_as_uint(bx)), "r"(__float_as_uint(by)));
}

// ---------------- fold W into tf32 hi/lo fragment planes (K32 chunks) ----------------
__global__ void fold_frag(
    const float* __restrict__ W0, const float* __restrict__ g0, const float* __restrict__ v0,
    const float* __restrict__ W1, const float* __restrict__ g1, const float* __restrict__ v1,
    const float* __restrict__ W2, const float* __restrict__ g2, const float* __restrict__ v2,
    const float* __restrict__ W3, const float* __restrict__ g3, const float* __restrict__ v3) {
    int t = blockIdx.x * 256 + threadIdx.x;   // 0 .. 20479
    int chunk = t >> 10;                      // 0..19
    int idx = t & 1023;
    const float *W, *g, *v;
    int koff;
    if (chunk < 4)       { W = W0; g = g0; v = v0; koff = chunk * 32; }
    else if (chunk < 8)  { W = W1; g = g1; v = v1; koff = (chunk - 4) * 32; }
    else if (chunk < 16) { W = W2; g = g2; v = v2; koff = (chunk - 8) * 32; }
    else                 { W = W3; g = g3; v = v3; koff = (chunk - 16) * 32; }
    int lane = idx & 31;
    int mt = (idx >> 5) & 7;
    int ks = idx >> 8;                        // 0..3
    int r0 = mt * 16 + (lane >> 2);
    int r1 = r0 + 8;
    int kg0 = koff + ks * 8 + (lane & 3);
    int kg1 = kg0 + 4;
    float s0 = g[kg0] * rsqrtf(v[kg0] + BN_EPS);
    float s1 = g[kg1] * rsqrtf(v[kg1] + BN_EPS);
    float v00 = W[kg0 * 128 + r0] * s0;
    float v10 = W[kg0 * 128 + r1] * s0;
    float v01 = W[kg1 * 128 + r0] * s1;
    float v11 = W[kg1 * 128 + r1] * s1;
    float h00 = tf32_rna(v00), h10 = tf32_rna(v10), h01 = tf32_rna(v01), h11 = tf32_rna(v11);
    float l00 = tf32_rna(v00 - h00), l10 = tf32_rna(v10 - h10);
    float l01 = tf32_rna(v01 - h01), l11 = tf32_rna(v11 - h11);
    float* base = g_Wfrag + chunk * 8192;
    *reinterpret_cast<float4*>(base + idx * 4)        = make_float4(h00, h10, h01, h11);
    *reinterpret_cast<float4*>(base + 4096 + idx * 4) = make_float4(l00, l10, l01, l11);
}

// b'[j] = bias[j] + sum_i (b_i - m_i*s_i) * W[i][j]
__global__ void fold_b_all(
    const float* __restrict__ g0, const float* __restrict__ b0, const float* __restrict__ m0, const float* __restrict__ v0, const float* __restrict__ W0, const float* __restrict__ s0, float* __restrict__ o0,
    const float* __restrict__ g1, const float* __restrict__ b1, const float* __restrict__ m1, const float* __restrict__ v1, const float* __restrict__ W1, const float* __restrict__ s1, float* __restrict__ o1,
    const float* __restrict__ g2, const float* __restrict__ b2, const float* __restrict__ m2, const float* __restrict__ v2, const float* __restrict__ W2, const float* __restrict__ s2, float* __restrict__ o2,
    const float* __restrict__ g3, const float* __restrict__ b3, const float* __restrict__ m3, const float* __restrict__ v3, const float* __restrict__ W3, const float* __restrict__ s3, float* __restrict__ o3) {
    int l = blockIdx.x;
    const float *g, *b, *m, *v, *W, *s;
    float* o;
    int K;
    switch (l) {
        case 0:  g = g0; b = b0; m = m0; v = v0; W = W0; s = s0; o = o0; K = 128; break;
        case 1:  g = g1; b = b1; m = m1; v = v1; W = W1; s = s1; o = o1; K = 128; break;
        case 2:  g = g2; b = b2; m = m2; v = v2; W = W2; s = s2; o = o2; K = 256; break;
        default: g = g3; b = b3; m = m3; v = v3; W = W3; s = s3; o = o3; K = 128; break;
    }
    int j = threadIdx.x;
    float acc0 = s[j], acc1 = 0.f;
    #pragma unroll 8
    for (int i = 0; i < K; i += 2) {
        float sc0 = g[i] * rsqrtf(v[i] + BN_EPS);
        float sc1 = g[i + 1] * rsqrtf(v[i + 1] + BN_EPS);
        acc0 = fmaf(b[i] - m[i] * sc0, W[i * 128 + j], acc0);
        acc1 = fmaf(b[i + 1] - m[i + 1] * sc1, W[(i + 1) * 128 + j], acc1);
    }
    o[j] = acc0 + acc1;
}

// ---------------- CSR build ----------------
__global__ void zero_cnt() {
    int i = blockIdx.x * 256 + threadIdx.x;
    if (i < NPAD) g_cntU[i] = 0;
}

__global__ void hist_kernel(const int* __restrict__ edges) {
    int e = blockIdx.x * 256 + threadIdx.x;
    if (e < EE) atomicAdd(&g_cntU[edges[e]], 1u);
}

// Block-level exclusive scan of counts; writes local-exclusive + block totals.
__global__ void scan_block() {
    __shared__ uint32_t wsum[8];
    int t = threadIdx.x, b = blockIdx.x;
    int i = b * 256 + t;
    uint32_t v = (i < NN) ? g_cntU[i] : 0;
    uint32_t x = v;
    #pragma unroll
    for (int d = 1; d < 32; d <<= 1) {
        uint32_t y = __shfl_up_sync(0xFFFFFFFFu, x, d);
        if ((t & 31) >= d) x += y;
    }
    if ((t & 31) == 31) wsum[t >> 5] = x;
    __syncthreads();
    uint32_t woff = 0;
    for (int j = 0; j < (t >> 5); j++) woff += wsum[j];
    if (i < NPAD) g_rowstart[i] = woff + x - v;
    if (t == 255) g_partials[b] = woff + x;
}

__global__ void scan_tops(int nblocks) {
    __shared__ uint32_t wsum[8];
    int t = threadIdx.x;
    uint32_t v = (t < nblocks) ? g_partials[t] : 0;
    uint32_t x = v;
    #pragma unroll
    for (int d = 1; d < 32; d <<= 1) {
        uint32_t y = __shfl_up_sync(0xFFFFFFFFu, x, d);
        if ((t & 31) >= d) x += y;
    }
    if ((t & 31) == 31) wsum[t >> 5] = x;
    __syncthreads();
    uint32_t woff = 0;
    for (int j = 0; j < (t >> 5); j++) woff += wsum[j];
    g_partials[t] = woff + x - v;   // exclusive
}

__global__ void scan_finalize() {
    int i = blockIdx.x * 256 + threadIdx.x;
    if (i < NPAD) {
        uint32_t r = g_rowstart[i] + g_partials[blockIdx.x];
        g_rowstart[i] = r;
        g_cursor[i] = r;
    }
}

__global__ void fill_kernel(const int* __restrict__ edges, const float* __restrict__ ew) {
    int e = blockIdx.x * 256 + threadIdx.x;
    if (e >= EE) return;
    int dst = edges[e];
    int src = edges[EE + e];
    uint32_t slot = atomicAdd(&g_cursor[dst], 1u);
    g_csrSrc[slot] = src;
    g_csrW[slot] = ew[e];
}

// ---------------- gather: one warp per node, MLP-4 row loads, writes MEAN ----------------
__global__ void __launch_bounds__(256)
gather_kernel() {
    int n = blockIdx.x * 8 + (threadIdx.x >> 5);
    int lane = threadIdx.x & 31;
    if (n >= NN) return;
    uint32_t s = g_rowstart[n];
    uint32_t c = g_cntU[n];
    float4 acc = make_float4(0.f, 0.f, 0.f, 0.f);
    uint32_t i = 0;
    for (; i + 4 <= c; i += 4) {
        int s0 = g_csrSrc[s + i];
        int s1 = g_csrSrc[s + i + 1];
        int s2 = g_csrSrc[s + i + 2];
        int s3 = g_csrSrc[s + i + 3];
        float w0 = g_csrW[s + i];
        float w1 = g_csrW[s + i + 1];
        float w2 = g_csrW[s + i + 2];
        float w3 = g_csrW[s + i + 3];
        float4 v0 = __ldg(reinterpret_cast<const float4*>(g_prep + (size_t)s0 * 128) + lane);
        float4 v1 = __ldg(reinterpret_cast<const float4*>(g_prep + (size_t)s1 * 128) + lane);
        float4 v2 = __ldg(reinterpret_cast<const float4*>(g_prep + (size_t)s2 * 128) + lane);
        float4 v3 = __ldg(reinterpret_cast<const float4*>(g_prep + (size_t)s3 * 128) + lane);
        acc.x += v0.x * w0 + v1.x * w1 + v2.x * w2 + v3.x * w3;
        acc.y += v0.y * w0 + v1.y * w1 + v2.y * w2 + v3.y * w3;
        acc.z += v0.z * w0 + v1.z * w1 + v2.z * w2 + v3.z * w3;
        acc.w += v0.w * w0 + v1.w * w1 + v2.w * w2 + v3.w * w3;
    }
    for (; i < c; i++) {
        int s0 = g_csrSrc[s + i];
        float w0 = g_csrW[s + i];
        float4 v0 = __ldg(reinterpret_cast<const float4*>(g_prep + (size_t)s0 * 128) + lane);
        acc.x += v0.x * w0; acc.y += v0.y * w0; acc.z += v0.z * w0; acc.w += v0.w * w0;
    }
    float inv = (c > 0) ? (1.0f / (float)c) : 0.f;
    acc.x *= inv; acc.y *= inv; acc.z *= inv; acc.w *= inv;
    reinterpret_cast<float4*>(g_agg + (size_t)n * 128)[lane] = acc;
}

// ---------------- tensor-core GEMM + bias + gelu (3xTF32, mt4 x nt4 warp tiles) -----
// Y[nrows,128] = gelu(X @ W' + b'), K in 32-wide chunks.
// Block: 256 threads, tile = 128 x-rows (N) x 128 w-cols (M). smem 64KB -> 2 blocks/SM.
// Warps: mg = wid&1 (M stripe of 64 = 4 m-tiles), ng = wid>>1 (N stripe of 32 = 4 n-tiles).
// Bytes/MMA = 1024/4 + 512/4 = 128 (was 170) -> crossbar relief.
template <int CHUNKS, bool CONCAT>
__global__ void __launch_bounds__(256, 2)
gemm_tc(const float* __restrict__ X0, const float* __restrict__ Wfrag,
        const float* __restrict__ B, float* __restrict__ Y, int nrows) {
    extern __shared__ float sm[];
    float* ws = sm;                      // 8192 floats: W frag chunk (hi 4096 | lo 4096)
    float* xf = sm + 8192;               // 8192 floats: 2048 B-frag float4 {b0h,b1h,b0l,b1l}

    const int tid = threadIdx.x;
    const int lane = tid & 31;
    const int wid = tid >> 5;
    const int mg = wid & 1;              // M group: 64 cols
    const int ng = wid >> 1;             // N group: 32 rows (0..3)
    const int row0 = blockIdx.x * 128;

    float c[4][4][4];
    #pragma unroll
    for (int mt = 0; mt < 4; mt++)
        #pragma unroll
        for (int nt = 0; nt < 4; nt++)
            #pragma unroll
            for (int j = 0; j < 4; j++) c[mt][nt][j] = 0.f;

    for (int cc = 0; cc < CHUNKS; cc++) {
        if (cc) __syncthreads();
        // ---- bulk-copy W frag chunk into smem (coalesced, fragment-ordered) ----
        {
            const float4* Wg = reinterpret_cast<const float4*>(Wfrag + cc * 8192);
            float4* Ws4 = reinterpret_cast<float4*>(ws);
            #pragma unroll
            for (int i = tid; i < 2048; i += 256) Ws4[i] = Wg[i];
        }
        // ---- x fragments straight from gmem: transpose + tf32 hi/lo split ----
        // entry e: le = e&31, ntg = (e>>5)&15 (global n-tile 0..15), ks = e>>9 (0..3)
        {
            const bool second = CONCAT && (cc >= CHUNKS / 2);
            const float* Xc = second ? g_agg : X0;
            const int koff = (CONCAT ? (cc % (CHUNKS / 2)) : cc) * 32;
            #pragma unroll
            for (int e = tid; e < 2048; e += 256) {
                int le = e & 31, ntg = (e >> 5) & 15, ks = e >> 9;
                int row = row0 + ntg * 8 + (le >> 2);
                int col = koff + ks * 8 + (le & 3);
                float v0 = 0.f, v1 = 0.f;
                if (row < nrows) {
                    const float* p = Xc + (size_t)row * 128 + col;
                    v0 = __ldg(p);
                    v1 = __ldg(p + 4);
                }
                float h0 = tf32_rna(v0), h1 = tf32_rna(v1);
                float l0 = tf32_rna(v0 - h0), l1 = tf32_rna(v1 - h1);
                *reinterpret_cast<float4*>(xf + e * 4) = make_float4(h0, h1, l0, l1);
            }
        }
        __syncthreads();

        // ---- mainloop: 4 k-steps, A and B from smem, 3 MMAs per tile (3xTF32) ----
        #pragma unroll
        for (int ks = 0; ks < 4; ks++) {
            float4 ah[4], al[4];
            #pragma unroll
            for (int mt = 0; mt < 4; mt++) {
                int aidx = (ks * 8 + mg * 4 + mt) * 32 + lane;
                ah[mt] = *reinterpret_cast<const float4*>(ws + aidx * 4);
                al[mt] = *reinterpret_cast<const float4*>(ws + 4096 + aidx * 4);
            }
            #pragma unroll
            for (int nt = 0; nt < 4; nt++) {
                float4 b = *reinterpret_cast<const float4*>(
                    xf + ((ks * 16 + ng * 4 + nt) * 32 + lane) * 4);
                #pragma unroll
                for (int mt = 0; mt < 4; mt++) {
                    mma_tf32(c[mt][nt], ah[mt], b.x, b.y);  // Ah * Bh
                    mma_tf32(c[mt][nt], ah[mt], b.z, b.w);  // Ah * Bl
                    mma_tf32(c[mt][nt], al[mt], b.x, b.y);  // Al * Bh
                }
            }
        }
    }

    // ---- epilogue: bias + gelu + transposed store ----
    #pragma unroll
    for (int mt = 0; mt < 4; mt++) {
        int col0 = (mg * 4 + mt) * 16 + (lane >> 2);
        float bb0 = B[col0];
        float bb8 = B[col0 + 8];
        #pragma unroll
        for (int nt = 0; nt < 4; nt++) {
            int rowx = row0 + (ng * 4 + nt) * 8 + 2 * (lane & 3);
            if (rowx < nrows) {
                Y[(size_t)rowx * 128 + col0]     = gelu_f(c[mt][nt][0] + bb0);
                Y[(size_t)rowx * 128 + col0 + 8] = gelu_f(c[mt][nt][2] + bb8);
            }
            if (rowx + 1 < nrows) {
                Y[(size_t)(rowx + 1) * 128 + col0]     = gelu_f(c[mt][nt][1] + bb0);
                Y[(size_t)(rowx + 1) * 128 + col0 + 8] = gelu_f(c[mt][nt][3] + bb8);
            }
        }
    }
}

// ---------------- launch ----------------
extern "C" void kernel_launch(void* const* d_in, const int* in_sizes, int n_in,
                              void* d_out, int out_size) {
    const float* node_repr = (const float*)d_in[0];
    const int*   edges     = (const int*)d_in[1];
    const float* edge_w    = (const float*)d_in[2];

    const float* p0g = (const float*)d_in[3];  const float* p0b = (const float*)d_in[4];
    const float* p0m = (const float*)d_in[5];  const float* p0v = (const float*)d_in[6];
    const float* p0W = (const float*)d_in[7];  const float* p0bias = (const float*)d_in[8];
    const float* p1g = (const float*)d_in[9];  const float* p1b = (const float*)d_in[10];
    const float* p1m = (const float*)d_in[11]; const float* p1v = (const float*)d_in[12];
    const float* p1W = (const float*)d_in[13]; const float* p1bias = (const float*)d_in[14];
    const float* u0g = (const float*)d_in[15]; const float* u0b = (const float*)d_in[16];
    const float* u0m = (const float*)d_in[17]; const float* u0v = (const float*)d_in[18];
    const float* u0W = (const float*)d_in[19]; const float* u0bias = (const float*)d_in[20];
    const float* u1g = (const float*)d_in[21]; const float* u1b = (const float*)d_in[22];
    const float* u1m = (const float*)d_in[23]; const float* u1v = (const float*)d_in[24];
    const float* u1W = (const float*)d_in[25]; const float* u1bias = (const float*)d_in[26];

    float *pWfrag, *pbp0, *pbp1, *pbu0, *pbu1, *pBufA, *pPrep;
    cudaGetSymbolAddress((void**)&pWfrag, g_Wfrag);
    cudaGetSymbolAddress((void**)&pbp0, g_bp0);
    cudaGetSymbolAddress((void**)&pbp1, g_bp1);
    cudaGetSymbolAddress((void**)&pbu0, g_bu0);
    cudaGetSymbolAddress((void**)&pbu1, g_bu1);
    cudaGetSymbolAddress((void**)&pBufA, g_bufA);
    cudaGetSymbolAddress((void**)&pPrep, g_prep);

    const int smemB = (8192 + 8192) * 4;   // 65536 B -> 2 blocks/SM
    cudaFuncSetAttribute(gemm_tc<4, false>, cudaFuncAttributeMaxDynamicSharedMemorySize, smemB);
    cudaFuncSetAttribute(gemm_tc<8, true>,  cudaFuncAttributeMaxDynamicSharedMemorySize, smemB);

    // 1) fold BN + tf32 hi/lo split into K32-chunk fragment planes, fold biases
    fold_frag<<<80, 256>>>(p0W, p0g, p0v,
                           p1W, p1g, p1v,
                           u0W, u0g, u0v,
                           u1W, u1g, u1v);
    fold_b_all<<<4, 128>>>(p0g, p0b, p0m, p0v, p0W, p0bias, pbp0,
                           p1g, p1b, p1m, p1v, p1W, p1bias, pbp1,
                           u0g, u0b, u0m, u0v, u0W, u0bias, pbu0,
                           u1g, u1b, u1m, u1v, u1W, u1bias, pbu1);

    // 2) CSR build (structure depends only on edges)
    zero_cnt<<<(NPAD + 255) / 256, 256>>>();
    hist_kernel<<<EE / 256, 256>>>(edges);
    scan_block<<<196, 256>>>();
    scan_tops<<<1, 256>>>(196);
    scan_finalize<<<196, 256>>>();

    const int gblocks = (NN + 127) / 128;  // 391
    // 3) prepare FFN per NODE (16x algebraic reduction vs per-edge)
    gemm_tc<4, false><<<gblocks, 256, smemB>>>(node_repr, pWfrag,             pbp0, pBufA, NN);
    gemm_tc<4, false><<<gblocks, 256, smemB>>>(pBufA,     pWfrag + 4 * 8192,  pbp1, pPrep, NN);

    // 4) fill CSR slots, then gather (writes pre-divided mean into g_agg)
    fill_kernel<<<EE / 256, 256>>>(edges, edge_w);
    gather_kernel<<<(NN + 7) / 8, 256>>>();

    // 5) update FFN: concat(node_repr, agg_mean) -> H, then H -> H (writes d_out)
    gemm_tc<8, true><<<gblocks, 256, smemB>>>(node_repr, pWfrag + 8 * 8192,   pbu0, pBufA, NN);
    gemm_tc<4, false><<<gblocks, 256, smemB>>>(pBufA,    pWfrag + 16 * 8192,  pbu1, (float*)d_out, NN);
}

// round 15
// speedup vs baseline: 1.4188x; 1.2991x over previous
#include <cuda_runtime.h>
#include <cuda_bf16.h>
#include <math.h>
#include <stdint.h>

#define NN 50000
#define EE 800000
#define BN_EPS 1e-3f
#define NPAD 50304

// ---------------- device scratch (no allocation allowed) ----------------
// W fragment buffers: 20 K32-chunks. Each chunk = 4096 uint32:
// bf16-HI plane 2048 (512 A-frag entries x uint4) then bf16-MID plane 2048.
// chunks 0-3: prep0, 4-7: prep1, 8-15: upd0 (K=256), 16-19: upd1
__device__ uint32_t g_Wfrag[20 * 4096];
__device__ float g_bp0[128];
__device__ float g_bp1[128];
__device__ float g_bu0[128];
__device__ float g_bu1[128];

__device__ float g_bufA[NN * 128];       // intermediate activations
__device__ float g_prep[NN * 128];       // prep FFN output (per-node messages)
__device__ float g_agg[NN * 128];        // aggregated MEAN (pre-divided)

// CSR scratch
__device__ uint32_t g_cntU[NPAD];
__device__ uint32_t g_rowstart[NPAD];
__device__ uint32_t g_cursor[NPAD];
__device__ uint32_t g_partials[256];
__device__ int      g_csrSrc[EE];
__device__ float    g_csrW[EE];

// ---------------- helpers ----------------
__device__ __forceinline__ float gelu_f(float x) {
    return 0.5f * x * (1.0f + erff(x * 0.70710678118654752f));
}
// split v into bf16 hi + bf16 mid (v ~ hi + mid, residual ~2^-16 rel)
__device__ __forceinline__ void bf16_split(float v, __nv_bfloat16& h, __nv_bfloat16& m) {
    h = __float2bfloat16(v);
    m = __float2bfloat16(v - __bfloat162float(h));
}
__device__ __forceinline__ uint32_t pack_bf(__nv_bfloat16 lo, __nv_bfloat16 hi) {
    __nv_bfloat162 p = __halves2bfloat162(lo, hi);
    return *reinterpret_cast<uint32_t*>(&p);
}
// D += A(16x16 bf16, row) * B(16x8 bf16, col); fp32 accum
__device__ __forceinline__ void mma_bf16(float* c, uint4 a, uint2 b) {
    asm("mma.sync.aligned.m16n8k16.row.col.f32.bf16.bf16.f32 "
        "{%0,%1,%2,%3},{%4,%5,%6,%7},{%8,%9},{%0,%1,%2,%3};"
        : "+f"(c[0]), "+f"(c[1]), "+f"(c[2]), "+f"(c[3])
        : "r"(a.x), "r"(a.y), "r"(a.z), "r"(a.w), "r"(b.x), "r"(b.y));
}

// ---------------- fold W: BN-fold + bf16 hi/mid split into k16 A-fragments ----------
// A = W'^T ([m=out-feature][k]). Entry idx within chunk = (ks*8 + mt)*32 + lane,
// ks in 0..1 (k16 steps of the K32 chunk), mt in 0..7 (m16 tiles).
// lane: g = lane>>2 (row in tile), tg = lane&3.
// a0 = {T(r0,k0),T(r0,k0+1)}, a1 = {T(r1,k0),...}, a2 = {T(r0,k0+8),...}, a3 = {T(r1,k0+8),...}
// with r0 = mt*16+g, r1 = r0+8, k0 = koff + ks*16 + tg*2.
__global__ void fold_frag(
    const float* __restrict__ W0, const float* __restrict__ g0, const float* __restrict__ v0,
    const float* __restrict__ W1, const float* __restrict__ g1, const float* __restrict__ v1,
    const float* __restrict__ W2, const float* __restrict__ g2, const float* __restrict__ v2,
    const float* __restrict__ W3, const float* __restrict__ g3, const float* __restrict__ v3) {
    int t = blockIdx.x * 256 + threadIdx.x;   // 0 .. 10239
    int chunk = t >> 9;                       // 0..19
    int idx = t & 511;
    const float *W, *g, *v;
    int koff;
    if (chunk < 4)       { W = W0; g = g0; v = v0; koff = chunk * 32; }
    else if (chunk < 8)  { W = W1; g = g1; v = v1; koff = (chunk - 4) * 32; }
    else if (chunk < 16) { W = W2; g = g2; v = v2; koff = (chunk - 8) * 32; }
    else                 { W = W3; g = g3; v = v3; koff = (chunk - 16) * 32; }
    int lane = idx & 31;
    int mt = (idx >> 5) & 7;
    int ks = idx >> 8;                        // 0..1
    int gi = lane >> 2, tg = lane & 3;
    int r0 = mt * 16 + gi, r1 = r0 + 8;
    int k0 = koff + ks * 16 + tg * 2;
    int k8 = k0 + 8;

    float s00 = g[k0] * rsqrtf(v[k0] + BN_EPS);
    float s01 = g[k0 + 1] * rsqrtf(v[k0 + 1] + BN_EPS);
    float s80 = g[k8] * rsqrtf(v[k8] + BN_EPS);
    float s81 = g[k8 + 1] * rsqrtf(v[k8 + 1] + BN_EPS);

    float va0x = W[k0 * 128 + r0] * s00,       va0y = W[(k0 + 1) * 128 + r0] * s01;
    float va1x = W[k0 * 128 + r1] * s00,       va1y = W[(k0 + 1) * 128 + r1] * s01;
    float va2x = W[k8 * 128 + r0] * s80,       va2y = W[(k8 + 1) * 128 + r0] * s81;
    float va3x = W[k8 * 128 + r1] * s80,       va3y = W[(k8 + 1) * 128 + r1] * s81;

    __nv_bfloat16 h, m;
    uint4 ah, am;
    __nv_bfloat16 h2, m2;
    bf16_split(va0x, h, m); bf16_split(va0y, h2, m2);
    ah.x = pack_bf(h, h2); am.x = pack_bf(m, m2);
    bf16_split(va1x, h, m); bf16_split(va1y, h2, m2);
    ah.y = pack_bf(h, h2); am.y = pack_bf(m, m2);
    bf16_split(va2x, h, m); bf16_split(va2y, h2, m2);
    ah.z = pack_bf(h, h2); am.z = pack_bf(m, m2);
    bf16_split(va3x, h, m); bf16_split(va3y, h2, m2);
    ah.w = pack_bf(h, h2); am.w = pack_bf(m, m2);

    uint32_t* base = g_Wfrag + chunk * 4096;
    reinterpret_cast<uint4*>(base)[idx] = ah;
    reinterpret_cast<uint4*>(base + 2048)[idx] = am;
}

// b'[j] = bias[j] + sum_i (b_i - m_i*s_i) * W[i][j]
__global__ void fold_b_all(
    const float* __restrict__ g0, const float* __restrict__ b0, const float* __restrict__ m0, const float* __restrict__ v0, const float* __restrict__ W0, const float* __restrict__ s0, float* __restrict__ o0,
    const float* __restrict__ g1, const float* __restrict__ b1, const float* __restrict__ m1, const float* __restrict__ v1, const float* __restrict__ W1, const float* __restrict__ s1, float* __restrict__ o1,
    const float* __restrict__ g2, const float* __restrict__ b2, const float* __restrict__ m2, const float* __restrict__ v2, const float* __restrict__ W2, const float* __restrict__ s2, float* __restrict__ o2,
    const float* __restrict__ g3, const float* __restrict__ b3, const float* __restrict__ m3, const float* __restrict__ v3, const float* __restrict__ W3, const float* __restrict__ s3, float* __restrict__ o3) {
    int l = blockIdx.x;
    const float *g, *b, *m, *v, *W, *s;
    float* o;
    int K;
    switch (l) {
        case 0:  g = g0; b = b0; m = m0; v = v0; W = W0; s = s0; o = o0; K = 128; break;
        case 1:  g = g1; b = b1; m = m1; v = v1; W = W1; s = s1; o = o1; K = 128; break;
        case 2:  g = g2; b = b2; m = m2; v = v2; W = W2; s = s2; o = o2; K = 256; break;
        default: g = g3; b = b3; m = m3; v = v3; W = W3; s = s3; o = o3; K = 128; break;
    }
    int j = threadIdx.x;
    float acc0 = s[j], acc1 = 0.f;
    #pragma unroll 8
    for (int i = 0; i < K; i += 2) {
        float sc0 = g[i] * rsqrtf(v[i] + BN_EPS);
        float sc1 = g[i + 1] * rsqrtf(v[i + 1] + BN_EPS);
        acc0 = fmaf(b[i] - m[i] * sc0, W[i * 128 + j], acc0);
        acc1 = fmaf(b[i + 1] - m[i + 1] * sc1, W[(i + 1) * 128 + j], acc1);
    }
    o[j] = acc0 + acc1;
}

// ---------------- CSR build ----------------
__global__ void zero_cnt() {
    int i = blockIdx.x * 256 + threadIdx.x;
    if (i < NPAD) g_cntU[i] = 0;
}

__global__ void hist_kernel(const int* __restrict__ edges) {
    int e = blockIdx.x * 256 + threadIdx.x;
    if (e < EE) atomicAdd(&g_cntU[edges[e]], 1u);
}

__global__ void scan_block() {
    __shared__ uint32_t wsum[8];
    int t = threadIdx.x, b = blockIdx.x;
    int i = b * 256 + t;
    uint32_t v = (i < NN) ? g_cntU[i] : 0;
    uint32_t x = v;
    #pragma unroll
    for (int d = 1; d < 32; d <<= 1) {
        uint32_t y = __shfl_up_sync(0xFFFFFFFFu, x, d);
        if ((t & 31) >= d) x += y;
    }
    if ((t & 31) == 31) wsum[t >> 5] = x;
    __syncthreads();
    uint32_t woff = 0;
    for (int j = 0; j < (t >> 5); j++) woff += wsum[j];
    if (i < NPAD) g_rowstart[i] = woff + x - v;
    if (t == 255) g_partials[b] = woff + x;
}

__global__ void scan_tops(int nblocks) {
    __shared__ uint32_t wsum[8];
    int t = threadIdx.x;
    uint32_t v = (t < nblocks) ? g_partials[t] : 0;
    uint32_t x = v;
    #pragma unroll
    for (int d = 1; d < 32; d <<= 1) {
        uint32_t y = __shfl_up_sync(0xFFFFFFFFu, x, d);
        if ((t & 31) >= d) x += y;
    }
    if ((t & 31) == 31) wsum[t >> 5] = x;
    __syncthreads();
    uint32_t woff = 0;
    for (int j = 0; j < (t >> 5); j++) woff += wsum[j];
    g_partials[t] = woff + x - v;
}

__global__ void scan_finalize() {
    int i = blockIdx.x * 256 + threadIdx.x;
    if (i < NPAD) {
        uint32_t r = g_rowstart[i] + g_partials[blockIdx.x];
        g_rowstart[i] = r;
        g_cursor[i] = r;
    }
}

__global__ void fill_kernel(const int* __restrict__ edges, const float* __restrict__ ew) {
    int e = blockIdx.x * 256 + threadIdx.x;
    if (e >= EE) return;
    int dst = edges[e];
    int src = edges[EE + e];
    uint32_t slot = atomicAdd(&g_cursor[dst], 1u);
    g_csrSrc[slot] = src;
    g_csrW[slot] = ew[e];
}

// ---------------- gather: one warp per node, MLP-4 row loads, writes MEAN ----------------
__global__ void __launch_bounds__(256)
gather_kernel() {
    int n = blockIdx.x * 8 + (threadIdx.x >> 5);
    int lane = threadIdx.x & 31;
    if (n >= NN) return;
    uint32_t s = g_rowstart[n];
    uint32_t c = g_cntU[n];
    float4 acc = make_float4(0.f, 0.f, 0.f, 0.f);
    uint32_t i = 0;
    for (; i + 4 <= c; i += 4) {
        int s0 = g_csrSrc[s + i];
        int s1 = g_csrSrc[s + i + 1];
        int s2 = g_csrSrc[s + i + 2];
        int s3 = g_csrSrc[s + i + 3];
        float w0 = g_csrW[s + i];
        float w1 = g_csrW[s + i + 1];
        float w2 = g_csrW[s + i + 2];
        float w3 = g_csrW[s + i + 3];
        float4 v0 = __ldg(reinterpret_cast<const float4*>(g_prep + (size_t)s0 * 128) + lane);
        float4 v1 = __ldg(reinterpret_cast<const float4*>(g_prep + (size_t)s1 * 128) + lane);
        float4 v2 = __ldg(reinterpret_cast<const float4*>(g_prep + (size_t)s2 * 128) + lane);
        float4 v3 = __ldg(reinterpret_cast<const float4*>(g_prep + (size_t)s3 * 128) + lane);
        acc.x += v0.x * w0 + v1.x * w1 + v2.x * w2 + v3.x * w3;
        acc.y += v0.y * w0 + v1.y * w1 + v2.y * w2 + v3.y * w3;
        acc.z += v0.z * w0 + v1.z * w1 + v2.z * w2 + v3.z * w3;
        acc.w += v0.w * w0 + v1.w * w1 + v2.w * w2 + v3.w * w3;
    }
    for (; i < c; i++) {
        int s0 = g_csrSrc[s + i];
        float w0 = g_csrW[s + i];
        float4 v0 = __ldg(reinterpret_cast<const float4*>(g_prep + (size_t)s0 * 128) + lane);
        acc.x += v0.x * w0; acc.y += v0.y * w0; acc.z += v0.z * w0; acc.w += v0.w * w0;
    }
    float inv = (c > 0) ? (1.0f / (float)c) : 0.f;
    acc.x *= inv; acc.y *= inv; acc.z *= inv; acc.w *= inv;
    reinterpret_cast<float4*>(g_agg + (size_t)n * 128)[lane] = acc;
}

// ---------------- tensor-core GEMM + bias + gelu (3xBF16 m16n8k16) ------------------
// Y[nrows,128] = gelu(X @ W' + b'), K in 32-wide chunks (2 k16-steps each).
// Block: 256 threads, tile = 128 x-rows (N) x 128 w-cols (M). smem 32KB -> 2 blocks/SM.
// Warps: mg = wid&1 (M stripe of 64 = 4 m16-tiles), ng = wid>>1 (N stripe of 32 = 4 n8-tiles).
// Per tile: 3 MMAs (Ah*Bh + Ah*Bm + Am*Bh); bf16 hi+mid split keeps rel err ~3e-5.
// k16 MMA doubles MACs/instr vs tf32 k8 -> half the MMA instructions of R13.
template <int CHUNKS, bool CONCAT>
__global__ void __launch_bounds__(256, 2)
gemm_tc(const float* __restrict__ X0, const uint32_t* __restrict__ Wfrag,
        const float* __restrict__ B, float* __restrict__ Y, int nrows) {
    extern __shared__ uint32_t sm[];
    uint32_t* ws = sm;                 // 4096: A frags (hi 0..2047 | mid 2048..4095), uint4 entries
    uint2* xf = reinterpret_cast<uint2*>(sm + 4096);  // 2048 uint2: B frags (hi 0..1023 | mid 1024..2047)

    const int tid = threadIdx.x;
    const int lane = tid & 31;
    const int wid = tid >> 5;
    const int mg = wid & 1;            // M group: 64 cols = 4 m16 tiles
    const int ng = wid >> 1;           // N group: 32 rows = 4 n8 tiles (0..3)
    const int row0 = blockIdx.x * 128;
    const int gi = lane >> 2, tg = lane & 3;

    float c[4][4][4];
    #pragma unroll
    for (int mt = 0; mt < 4; mt++)
        #pragma unroll
        for (int nt = 0; nt < 4; nt++)
            #pragma unroll
            for (int j = 0; j < 4; j++) c[mt][nt][j] = 0.f;

    for (int cc = 0; cc < CHUNKS; cc++) {
        if (cc) __syncthreads();
        // ---- copy W frag chunk (fragment-ordered in gmem) ----
        {
            const uint4* Wg = reinterpret_cast<const uint4*>(Wfrag + cc * 4096);
            uint4* Ws = reinterpret_cast<uint4*>(ws);
            #pragma unroll
            for (int i = tid; i < 1024; i += 256) Ws[i] = Wg[i];
        }
        // ---- x B-fragments straight from gmem: bf16 hi/mid split ----
        // entry e = (ks*16 + ntg)*32 + lane_e; ks in 0..1, ntg in 0..15.
        // b0 = {x[r][k], x[r][k+1]}, b1 = {x[r][k+8], x[r][k+9]},
        // r = row0 + ntg*8 + g, k = koff + ks*16 + tg*2.
        {
            const bool second = CONCAT && (cc >= CHUNKS / 2);
            const float* Xc = second ? g_agg : X0;
            const int koff = (CONCAT ? (cc % (CHUNKS / 2)) : cc) * 32;
            #pragma unroll
            for (int e = tid; e < 1024; e += 256) {
                int le = e & 31, ntg = (e >> 5) & 15, ks = e >> 9;
                int row = row0 + ntg * 8 + (le >> 2);
                int k = koff + ks * 16 + (le & 3) * 2;
                float2 v0 = make_float2(0.f, 0.f), v1 = make_float2(0.f, 0.f);
                if (row < nrows) {
                    const float* p = Xc + (size_t)row * 128 + k;
                    v0 = *reinterpret_cast<const float2*>(p);
                    v1 = *reinterpret_cast<const float2*>(p + 8);
                }
                __nv_bfloat16 h0, m0, h1, m1;
                uint2 bh, bm;
                bf16_split(v0.x, h0, m0); bf16_split(v0.y, h1, m1);
                bh.x = pack_bf(h0, h1); bm.x = pack_bf(m0, m1);
                bf16_split(v1.x, h0, m0); bf16_split(v1.y, h1, m1);
                bh.y = pack_bf(h0, h1); bm.y = pack_bf(m0, m1);
                xf[e] = bh;
                xf[1024 + e] = bm;
            }
        }
        __syncthreads();

        // ---- mainloop: 2 k16-steps; per (mt,nt): 3 bf16 MMAs ----
        #pragma unroll
        for (int ks = 0; ks < 2; ks++) {
            uint4 ah[4], am[4];
            #pragma unroll
            for (int mt = 0; mt < 4; mt++) {
                int aidx = (ks * 8 + mg * 4 + mt) * 32 + lane;
                ah[mt] = reinterpret_cast<const uint4*>(ws)[aidx];
                am[mt] = reinterpret_cast<const uint4*>(ws + 2048)[aidx];
            }
            #pragma unroll
            for (int nt = 0; nt < 4; nt++) {
                int bidx = (ks * 16 + ng * 4 + nt) * 32 + lane;
                uint2 bh = xf[bidx];
                uint2 bm = xf[1024 + bidx];
                #pragma unroll
                for (int mt = 0; mt < 4; mt++) {
                    mma_bf16(c[mt][nt], ah[mt], bh);  // Ah * Bh
                    mma_bf16(c[mt][nt], ah[mt], bm);  // Ah * Bm
                    mma_bf16(c[mt][nt], am[mt], bh);  // Am * Bh
                }
            }
        }
    }

    // ---- epilogue: bias + gelu + transposed store ----
    // C(m,n): c0=(g,2t) c1=(g,2t+1) c2=(g+8,2t) c3=(g+8,2t+1); m = w-col, n = x-row.
    #pragma unroll
    for (int mt = 0; mt < 4; mt++) {
        int col0 = (mg * 4 + mt) * 16 + gi;
        float bb0 = B[col0];
        float bb8 = B[col0 + 8];
        #pragma unroll
        for (int nt = 0; nt < 4; nt++) {
            int rowx = row0 + (ng * 4 + nt) * 8 + 2 * tg;
            if (rowx < nrows) {
                Y[(size_t)rowx * 128 + col0]     = gelu_f(c[mt][nt][0] + bb0);
                Y[(size_t)rowx * 128 + col0 + 8] = gelu_f(c[mt][nt][2] + bb8);
            }
            if (rowx + 1 < nrows) {
                Y[(size_t)(rowx + 1) * 128 + col0]     = gelu_f(c[mt][nt][1] + bb0);
                Y[(size_t)(rowx + 1) * 128 + col0 + 8] = gelu_f(c[mt][nt][3] + bb8);
            }
        }
    }
}

// ---------------- launch ----------------
extern "C" void kernel_launch(void* const* d_in, const int* in_sizes, int n_in,
                              void* d_out, int out_size) {
    const float* node_repr = (const float*)d_in[0];
    const int*   edges     = (const int*)d_in[1];
    const float* edge_w    = (const float*)d_in[2];

    const float* p0g = (const float*)d_in[3];  const float* p0b = (const float*)d_in[4];
    const float* p0m = (const float*)d_in[5];  const float* p0v = (const float*)d_in[6];
    const float* p0W = (const float*)d_in[7];  const float* p0bias = (const float*)d_in[8];
    const float* p1g = (const float*)d_in[9];  const float* p1b = (const float*)d_in[10];
    const float* p1m = (const float*)d_in[11]; const float* p1v = (const float*)d_in[12];
    const float* p1W = (const float*)d_in[13]; const float* p1bias = (const float*)d_in[14];
    const float* u0g = (const float*)d_in[15]; const float* u0b = (const float*)d_in[16];
    const float* u0m = (const float*)d_in[17]; const float* u0v = (const float*)d_in[18];
    const float* u0W = (const float*)d_in[19]; const float* u0bias = (const float*)d_in[20];
    const float* u1g = (const float*)d_in[21]; const float* u1b = (const float*)d_in[22];
    const float* u1m = (const float*)d_in[23]; const float* u1v = (const float*)d_in[24];
    const float* u1W = (const float*)d_in[25]; const float* u1bias = (const float*)d_in[26];

    uint32_t* pWfrag;
    float *pbp0, *pbp1, *pbu0, *pbu1, *pBufA, *pPrep;
    cudaGetSymbolAddress((void**)&pWfrag, g_Wfrag);
    cudaGetSymbolAddress((void**)&pbp0, g_bp0);
    cudaGetSymbolAddress((void**)&pbp1, g_bp1);
    cudaGetSymbolAddress((void**)&pbu0, g_bu0);
    cudaGetSymbolAddress((void**)&pbu1, g_bu1);
    cudaGetSymbolAddress((void**)&pBufA, g_bufA);
    cudaGetSymbolAddress((void**)&pPrep, g_prep);

    const int smemB = (4096 + 4096) * 4;   // 32768 B
    cudaFuncSetAttribute(gemm_tc<4, false>, cudaFuncAttributeMaxDynamicSharedMemorySize, smemB);
    cudaFuncSetAttribute(gemm_tc<8, true>,  cudaFuncAttributeMaxDynamicSharedMemorySize, smemB);

    // 1) fold BN + bf16 hi/mid split into k16 A-fragments, fold biases
    fold_frag<<<40, 256>>>(p0W, p0g, p0v,
                           p1W, p1g, p1v,
                           u0W, u0g, u0v,
                           u1W, u1g, u1v);
    fold_b_all<<<4, 128>>>(p0g, p0b, p0m, p0v, p0W, p0bias, pbp0,
                           p1g, p1b, p1m, p1v, p1W, p1bias, pbp1,
                           u0g, u0b, u0m, u0v, u0W, u0bias, pbu0,
                           u1g, u1b, u1m, u1v, u1W, u1bias, pbu1);

    // 2) CSR build
    zero_cnt<<<(NPAD + 255) / 256, 256>>>();
    hist_kernel<<<EE / 256, 256>>>(edges);
    scan_block<<<196, 256>>>();
    scan_tops<<<1, 256>>>(196);
    scan_finalize<<<196, 256>>>();

    const int gblocks = (NN + 127) / 128;  // 391
    // 3) prepare FFN per NODE (16x algebraic reduction vs per-edge)
    gemm_tc<4, false><<<gblocks, 256, smemB>>>(node_repr, pWfrag,             pbp0, pBufA, NN);
    gemm_tc<4, false><<<gblocks, 256, smemB>>>(pBufA,     pWfrag + 4 * 4096,  pbp1, pPrep, NN);

    // 4) fill CSR slots, gather (writes pre-divided mean)
    fill_kernel<<<EE / 256, 256>>>(edges, edge_w);
    gather_kernel<<<(NN + 7) / 8, 256>>>();

    // 5) update FFN: concat(node_repr, agg_mean) -> H, then H -> H (writes d_out)
    gemm_tc<8, true><<<gblocks, 256, smemB>>>(node_repr, pWfrag + 8 * 4096,   pbu0, pBufA, NN);
    gemm_tc<4, false><<<gblocks, 256, smemB>>>(pBufA,    pWfrag + 16 * 4096,  pbu1, (float*)d_out, NN);
}

// round 17
// speedup vs baseline: 1.5368x; 1.0832x over previous
#include <cuda_runtime.h>
#include <cuda_bf16.h>
#include <math.h>
#include <stdint.h>

#define NN 50000
#define EE 800000
#define BN_EPS 1e-3f
#define NPAD 50304

// ---------------- device scratch (no allocation allowed) ----------------
// W fragment buffers: 20 K32-chunks. Each chunk = 4096 uint32:
// bf16-HI plane 2048 (512 A-frag entries x uint4) then bf16-MID plane 2048.
// chunks 0-3: prep0, 4-7: prep1, 8-15: upd0 (K=256), 16-19: upd1
__device__ uint32_t g_Wfrag[20 * 4096];
__device__ float g_bp0[128];
__device__ float g_bp1[128];
__device__ float g_bu0[128];
__device__ float g_bu1[128];

__device__ float g_prep[NN * 128];       // prep FFN output (per-node messages)
__device__ float g_agg[NN * 128];        // aggregated MEAN (pre-divided)

// CSR scratch
__device__ uint32_t g_cntU[NPAD];
__device__ uint32_t g_rowstart[NPAD];
__device__ uint32_t g_cursor[NPAD];
__device__ uint32_t g_partials[256];
__device__ int      g_csrSrc[EE];
__device__ float    g_csrW[EE];

// ---------------- helpers ----------------
__device__ __forceinline__ float gelu_f(float x) {
    return 0.5f * x * (1.0f + erff(x * 0.70710678118654752f));
}
__device__ __forceinline__ void bf16_split(float v, __nv_bfloat16& h, __nv_bfloat16& m) {
    h = __float2bfloat16(v);
    m = __float2bfloat16(v - __bfloat162float(h));
}
__device__ __forceinline__ uint32_t pack_bf(__nv_bfloat16 lo, __nv_bfloat16 hi) {
    __nv_bfloat162 p = __halves2bfloat162(lo, hi);
    return *reinterpret_cast<uint32_t*>(&p);
}
// D += A(16x16 bf16, row) * B(16x8 bf16, col); fp32 accum
__device__ __forceinline__ void mma_bf16(float* c, uint4 a, uint2 b) {
    asm("mma.sync.aligned.m16n8k16.row.col.f32.bf16.bf16.f32 "
        "{%0,%1,%2,%3},{%4,%5,%6,%7},{%8,%9},{%0,%1,%2,%3};"
        : "+f"(c[0]), "+f"(c[1]), "+f"(c[2]), "+f"(c[3])
        : "r"(a.x), "r"(a.y), "r"(a.z), "r"(a.w), "r"(b.x), "r"(b.y));
}

// ---------------- fold W: BN-fold + bf16 hi/mid split into k16 A-fragments ----------
__global__ void fold_frag(
    const float* __restrict__ W0, const float* __restrict__ g0, const float* __restrict__ v0,
    const float* __restrict__ W1, const float* __restrict__ g1, const float* __restrict__ v1,
    const float* __restrict__ W2, const float* __restrict__ g2, const float* __restrict__ v2,
    const float* __restrict__ W3, const float* __restrict__ g3, const float* __restrict__ v3) {
    int t = blockIdx.x * 256 + threadIdx.x;   // 0 .. 10239
    int chunk = t >> 9;                       // 0..19
    int idx = t & 511;
    const float *W, *g, *v;
    int koff;
    if (chunk < 4)       { W = W0; g = g0; v = v0; koff = chunk * 32; }
    else if (chunk < 8)  { W = W1; g = g1; v = v1; koff = (chunk - 4) * 32; }
    else if (chunk < 16) { W = W2; g = g2; v = v2; koff = (chunk - 8) * 32; }
    else                 { W = W3; g = g3; v = v3; koff = (chunk - 16) * 32; }
    int lane = idx & 31;
    int mt = (idx >> 5) & 7;
    int ks = idx >> 8;                        // 0..1
    int gi = lane >> 2, tg = lane & 3;
    int r0 = mt * 16 + gi, r1 = r0 + 8;
    int k0 = koff + ks * 16 + tg * 2;
    int k8 = k0 + 8;

    float s00 = g[k0] * rsqrtf(v[k0] + BN_EPS);
    float s01 = g[k0 + 1] * rsqrtf(v[k0 + 1] + BN_EPS);
    float s80 = g[k8] * rsqrtf(v[k8] + BN_EPS);
    float s81 = g[k8 + 1] * rsqrtf(v[k8 + 1] + BN_EPS);

    float va0x = W[k0 * 128 + r0] * s00,       va0y = W[(k0 + 1) * 128 + r0] * s01;
    float va1x = W[k0 * 128 + r1] * s00,       va1y = W[(k0 + 1) * 128 + r1] * s01;
    float va2x = W[k8 * 128 + r0] * s80,       va2y = W[(k8 + 1) * 128 + r0] * s81;
    float va3x = W[k8 * 128 + r1] * s80,       va3y = W[(k8 + 1) * 128 + r1] * s81;

    __nv_bfloat16 h, m, h2, m2;
    uint4 ah, am;
    bf16_split(va0x, h, m); bf16_split(va0y, h2, m2);
    ah.x = pack_bf(h, h2); am.x = pack_bf(m, m2);
    bf16_split(va1x, h, m); bf16_split(va1y, h2, m2);
    ah.y = pack_bf(h, h2); am.y = pack_bf(m, m2);
    bf16_split(va2x, h, m); bf16_split(va2y, h2, m2);
    ah.z = pack_bf(h, h2); am.z = pack_bf(m, m2);
    bf16_split(va3x, h, m); bf16_split(va3y, h2, m2);
    ah.w = pack_bf(h, h2); am.w = pack_bf(m, m2);

    uint32_t* base = g_Wfrag + chunk * 4096;
    reinterpret_cast<uint4*>(base)[idx] = ah;
    reinterpret_cast<uint4*>(base + 2048)[idx] = am;
}

// b'[j] = bias[j] + sum_i (b_i - m_i*s_i) * W[i][j]
__global__ void fold_b_all(
    const float* __restrict__ g0, const float* __restrict__ b0, const float* __restrict__ m0, const float* __restrict__ v0, const float* __restrict__ W0, const float* __restrict__ s0, float* __restrict__ o0,
    const float* __restrict__ g1, const float* __restrict__ b1, const float* __restrict__ m1, const float* __restrict__ v1, const float* __restrict__ W1, const float* __restrict__ s1, float* __restrict__ o1,
    const float* __restrict__ g2, const float* __restrict__ b2, const float* __restrict__ m2, const float* __restrict__ v2, const float* __restrict__ W2, const float* __restrict__ s2, float* __restrict__ o2,
    const float* __restrict__ g3, const float* __restrict__ b3, const float* __restrict__ m3, const float* __restrict__ v3, const float* __restrict__ W3, const float* __restrict__ s3, float* __restrict__ o3) {
    int l = blockIdx.x;
    const float *g, *b, *m, *v, *W, *s;
    float* o;
    int K;
    switch (l) {
        case 0:  g = g0; b = b0; m = m0; v = v0; W = W0; s = s0; o = o0; K = 128; break;
        case 1:  g = g1; b = b1; m = m1; v = v1; W = W1; s = s1; o = o1; K = 128; break;
        case 2:  g = g2; b = b2; m = m2; v = v2; W = W2; s = s2; o = o2; K = 256; break;
        default: g = g3; b = b3; m = m3; v = v3; W = W3; s = s3; o = o3; K = 128; break;
    }
    int j = threadIdx.x;
    float acc0 = s[j], acc1 = 0.f;
    #pragma unroll 8
    for (int i = 0; i < K; i += 2) {
        float sc0 = g[i] * rsqrtf(v[i] + BN_EPS);
        float sc1 = g[i + 1] * rsqrtf(v[i + 1] + BN_EPS);
        acc0 = fmaf(b[i] - m[i] * sc0, W[i * 128 + j], acc0);
        acc1 = fmaf(b[i + 1] - m[i + 1] * sc1, W[(i + 1) * 128 + j], acc1);
    }
    o[j] = acc0 + acc1;
}

// ---------------- CSR build ----------------
__global__ void zero_cnt() {
    int i = blockIdx.x * 256 + threadIdx.x;
    if (i < NPAD) g_cntU[i] = 0;
}

// 4 edges per thread via int4
__global__ void hist_kernel(const int* __restrict__ edges) {
    int i = blockIdx.x * 256 + threadIdx.x;
    if (i * 4 >= EE) return;
    int4 d = __ldg(reinterpret_cast<const int4*>(edges) + i);
    atomicAdd(&g_cntU[d.x], 1u);
    atomicAdd(&g_cntU[d.y], 1u);
    atomicAdd(&g_cntU[d.z], 1u);
    atomicAdd(&g_cntU[d.w], 1u);
}

__global__ void scan_block() {
    __shared__ uint32_t wsum[8];
    int t = threadIdx.x, b = blockIdx.x;
    int i = b * 256 + t;
    uint32_t v = (i < NN) ? g_cntU[i] : 0;
    uint32_t x = v;
    #pragma unroll
    for (int d = 1; d < 32; d <<= 1) {
        uint32_t y = __shfl_up_sync(0xFFFFFFFFu, x, d);
        if ((t & 31) >= d) x += y;
    }
    if ((t & 31) == 31) wsum[t >> 5] = x;
    __syncthreads();
    uint32_t woff = 0;
    for (int j = 0; j < (t >> 5); j++) woff += wsum[j];
    if (i < NPAD) g_rowstart[i] = woff + x - v;
    if (t == 255) g_partials[b] = woff + x;
}

__global__ void scan_tops(int nblocks) {
    __shared__ uint32_t wsum[8];
    int t = threadIdx.x;
    uint32_t v = (t < nblocks) ? g_partials[t] : 0;
    uint32_t x = v;
    #pragma unroll
    for (int d = 1; d < 32; d <<= 1) {
        uint32_t y = __shfl_up_sync(0xFFFFFFFFu, x, d);
        if ((t & 31) >= d) x += y;
    }
    if ((t & 31) == 31) wsum[t >> 5] = x;
    __syncthreads();
    uint32_t woff = 0;
    for (int j = 0; j < (t >> 5); j++) woff += wsum[j];
    g_partials[t] = woff + x - v;
}

__global__ void scan_finalize() {
    int i = blockIdx.x * 256 + threadIdx.x;
    if (i < NPAD) {
        uint32_t r = g_rowstart[i] + g_partials[blockIdx.x];
        g_rowstart[i] = r;
        g_cursor[i] = r;
    }
}

// 4 edges per thread via int4
__global__ void fill_kernel(const int* __restrict__ edges, const float* __restrict__ ew) {
    int i = blockIdx.x * 256 + threadIdx.x;
    if (i * 4 >= EE) return;
    int4 dst = __ldg(reinterpret_cast<const int4*>(edges) + i);
    int4 src = __ldg(reinterpret_cast<const int4*>(edges + EE) + i);
    float4 w = __ldg(reinterpret_cast<const float4*>(ew) + i);
    uint32_t s0 = atomicAdd(&g_cursor[dst.x], 1u);
    uint32_t s1 = atomicAdd(&g_cursor[dst.y], 1u);
    uint32_t s2 = atomicAdd(&g_cursor[dst.z], 1u);
    uint32_t s3 = atomicAdd(&g_cursor[dst.w], 1u);
    g_csrSrc[s0] = src.x; g_csrW[s0] = w.x;
    g_csrSrc[s1] = src.y; g_csrW[s1] = w.y;
    g_csrSrc[s2] = src.z; g_csrW[s2] = w.z;
    g_csrSrc[s3] = src.w; g_csrW[s3] = w.w;
}

// ---------------- gather: one warp per node, MLP-4 row loads, writes MEAN ----------------
__global__ void __launch_bounds__(256)
gather_kernel() {
    int n = blockIdx.x * 8 + (threadIdx.x >> 5);
    int lane = threadIdx.x & 31;
    if (n >= NN) return;
    uint32_t s = g_rowstart[n];
    uint32_t c = g_cntU[n];
    float4 acc = make_float4(0.f, 0.f, 0.f, 0.f);
    uint32_t i = 0;
    for (; i + 4 <= c; i += 4) {
        int s0 = g_csrSrc[s + i];
        int s1 = g_csrSrc[s + i + 1];
        int s2 = g_csrSrc[s + i + 2];
        int s3 = g_csrSrc[s + i + 3];
        float w0 = g_csrW[s + i];
        float w1 = g_csrW[s + i + 1];
        float w2 = g_csrW[s + i + 2];
        float w3 = g_csrW[s + i + 3];
        float4 v0 = __ldg(reinterpret_cast<const float4*>(g_prep + (size_t)s0 * 128) + lane);
        float4 v1 = __ldg(reinterpret_cast<const float4*>(g_prep + (size_t)s1 * 128) + lane);
        float4 v2 = __ldg(reinterpret_cast<const float4*>(g_prep + (size_t)s2 * 128) + lane);
        float4 v3 = __ldg(reinterpret_cast<const float4*>(g_prep + (size_t)s3 * 128) + lane);
        acc.x += v0.x * w0 + v1.x * w1 + v2.x * w2 + v3.x * w3;
        acc.y += v0.y * w0 + v1.y * w1 + v2.y * w2 + v3.y * w3;
        acc.z += v0.z * w0 + v1.z * w1 + v2.z * w2 + v3.z * w3;
        acc.w += v0.w * w0 + v1.w * w1 + v2.w * w2 + v3.w * w3;
    }
    for (; i < c; i++) {
        int s0 = g_csrSrc[s + i];
        float w0 = g_csrW[s + i];
        float4 v0 = __ldg(reinterpret_cast<const float4*>(g_prep + (size_t)s0 * 128) + lane);
        acc.x += v0.x * w0; acc.y += v0.y * w0; acc.z += v0.z * w0; acc.w += v0.w * w0;
    }
    float inv = (c > 0) ? (1.0f / (float)c) : 0.f;
    acc.x *= inv; acc.y *= inv; acc.z *= inv; acc.w *= inv;
    reinterpret_cast<float4*>(g_agg + (size_t)n * 128)[lane] = acc;
}

// ---------------- fused 2-layer FFN: Y = gelu(gelu(X@W0'+b0')@W1'+b1') ----------------
// 3xBF16 m16n8k16 tensor cores. Block: 256 threads, tile = 128 x-rows x 128 cols.
// Layer 0 (K = CH0*32; CONCAT: first half node_repr, second half g_agg) accumulates,
// epilogue writes gelu result into smem ys (128 x 132 fp32, conflict-free), then
// layer 1 (K=128) stages x-fragments straight from ys (LDS) and writes Y to gmem.
// smem layout (uint32 units): ws [0,4096) | xf = 2048 uint2 [4096,8192) | ys [8192,25088).
// Total 100352 B -> 2 blocks/SM.
#define YS_LD 132
template <int CH0, bool CONCAT>
__global__ void __launch_bounds__(256, 2)
gemm_fused(const float* __restrict__ X0,
           const uint32_t* __restrict__ Wf0, const float* __restrict__ B0,
           const uint32_t* __restrict__ Wf1, const float* __restrict__ B1,
           float* __restrict__ Y, int nrows) {
    extern __shared__ uint32_t sm[];
    uint32_t* ws = sm;                                   // 4096 uint32: A frags (hi|mid)
    uint2* xf = reinterpret_cast<uint2*>(sm + 4096);     // 2048 uint2 = 4096 uint32
    float* ys = reinterpret_cast<float*>(sm + 8192);     // 128*132 fp32 layer-0 out

    const int tid = threadIdx.x;
    const int lane = tid & 31;
    const int wid = tid >> 5;
    const int mg = wid & 1;            // M group: 64 cols = 4 m16 tiles
    const int ng = wid >> 1;           // N group: 32 rows = 4 n8 tiles
    const int row0 = blockIdx.x * 128;
    const int gi = lane >> 2, tg = lane & 3;

    float c[4][4][4];

    // ================= LAYER 0 =================
    #pragma unroll
    for (int mt = 0; mt < 4; mt++)
        #pragma unroll
        for (int nt = 0; nt < 4; nt++)
            #pragma unroll
            for (int j = 0; j < 4; j++) c[mt][nt][j] = 0.f;

    for (int cc = 0; cc < CH0; cc++) {
        if (cc) __syncthreads();
        {
            const uint4* Wg = reinterpret_cast<const uint4*>(Wf0 + cc * 4096);
            uint4* Ws = reinterpret_cast<uint4*>(ws);
            #pragma unroll
            for (int i = tid; i < 1024; i += 256) Ws[i] = Wg[i];
        }
        {
            const bool second = CONCAT && (cc >= CH0 / 2);
            const float* Xc = second ? g_agg : X0;
            const int koff = (CONCAT ? (cc % (CH0 / 2)) : cc) * 32;
            #pragma unroll
            for (int e = tid; e < 1024; e += 256) {
                int le = e & 31, ntg = (e >> 5) & 15, ks = e >> 9;
                int row = row0 + ntg * 8 + (le >> 2);
                int k = koff + ks * 16 + (le & 3) * 2;
                float2 v0 = make_float2(0.f, 0.f), v1 = make_float2(0.f, 0.f);
                if (row < nrows) {
                    const float* p = Xc + (size_t)row * 128 + k;
                    v0 = *reinterpret_cast<const float2*>(p);
                    v1 = *reinterpret_cast<const float2*>(p + 8);
                }
                __nv_bfloat16 h0, m0, h1, m1;
                uint2 bh, bm;
                bf16_split(v0.x, h0, m0); bf16_split(v0.y, h1, m1);
                bh.x = pack_bf(h0, h1); bm.x = pack_bf(m0, m1);
                bf16_split(v1.x, h0, m0); bf16_split(v1.y, h1, m1);
                bh.y = pack_bf(h0, h1); bm.y = pack_bf(m0, m1);
                xf[e] = bh;
                xf[1024 + e] = bm;
            }
        }
        __syncthreads();

        #pragma unroll
        for (int ks = 0; ks < 2; ks++) {
            uint4 ah[4], am[4];
            #pragma unroll
            for (int mt = 0; mt < 4; mt++) {
                int aidx = (ks * 8 + mg * 4 + mt) * 32 + lane;
                ah[mt] = reinterpret_cast<const uint4*>(ws)[aidx];
                am[mt] = reinterpret_cast<const uint4*>(ws + 2048)[aidx];
            }
            #pragma unroll
            for (int nt = 0; nt < 4; nt++) {
                int bidx = (ks * 16 + ng * 4 + nt) * 32 + lane;
                uint2 bh = xf[bidx];
                uint2 bm = xf[1024 + bidx];
                #pragma unroll
                for (int mt = 0; mt < 4; mt++) {
                    mma_bf16(c[mt][nt], ah[mt], bh);
                    mma_bf16(c[mt][nt], ah[mt], bm);
                    mma_bf16(c[mt][nt], am[mt], bh);
                }
            }
        }
    }
    __syncthreads();   // mainloop reads of ws/xf done everywhere

    // epilogue 0: bias + gelu -> ys (write ALL 128 rows; conflict-free: bank=(4r+c)%32)
    #pragma unroll
    for (int mt = 0; mt < 4; mt++) {
        int col0 = (mg * 4 + mt) * 16 + gi;
        float bb0 = B0[col0];
        float bb8 = B0[col0 + 8];
        #pragma unroll
        for (int nt = 0; nt < 4; nt++) {
            int rl = (ng * 4 + nt) * 8 + 2 * tg;
            ys[rl * YS_LD + col0]           = gelu_f(c[mt][nt][0] + bb0);
            ys[rl * YS_LD + col0 + 8]       = gelu_f(c[mt][nt][2] + bb8);
            ys[(rl + 1) * YS_LD + col0]     = gelu_f(c[mt][nt][1] + bb0);
            ys[(rl + 1) * YS_LD + col0 + 8] = gelu_f(c[mt][nt][3] + bb8);
        }
    }
    __syncthreads();

    // ================= LAYER 1 (K=128, x from ys) =================
    #pragma unroll
    for (int mt = 0; mt < 4; mt++)
        #pragma unroll
        for (int nt = 0; nt < 4; nt++)
            #pragma unroll
            for (int j = 0; j < 4; j++) c[mt][nt][j] = 0.f;

    for (int cc = 0; cc < 4; cc++) {
        if (cc) __syncthreads();
        {
            const uint4* Wg = reinterpret_cast<const uint4*>(Wf1 + cc * 4096);
            uint4* Ws = reinterpret_cast<uint4*>(ws);
            #pragma unroll
            for (int i = tid; i < 1024; i += 256) Ws[i] = Wg[i];
        }
        {
            const int koff = cc * 32;
            #pragma unroll
            for (int e = tid; e < 1024; e += 256) {
                int le = e & 31, ntg = (e >> 5) & 15, ks = e >> 9;
                int rl = ntg * 8 + (le >> 2);
                int k = koff + ks * 16 + (le & 3) * 2;
                float2 v0 = *reinterpret_cast<const float2*>(ys + rl * YS_LD + k);
                float2 v1 = *reinterpret_cast<const float2*>(ys + rl * YS_LD + k + 8);
                __nv_bfloat16 h0, m0, h1, m1;
                uint2 bh, bm;
                bf16_split(v0.x, h0, m0); bf16_split(v0.y, h1, m1);
                bh.x = pack_bf(h0, h1); bm.x = pack_bf(m0, m1);
                bf16_split(v1.x, h0, m0); bf16_split(v1.y, h1, m1);
                bh.y = pack_bf(h0, h1); bm.y = pack_bf(m0, m1);
                xf[e] = bh;
                xf[1024 + e] = bm;
            }
        }
        __syncthreads();

        #pragma unroll
        for (int ks = 0; ks < 2; ks++) {
            uint4 ah[4], am[4];
            #pragma unroll
            for (int mt = 0; mt < 4; mt++) {
                int aidx = (ks * 8 + mg * 4 + mt) * 32 + lane;
                ah[mt] = reinterpret_cast<const uint4*>(ws)[aidx];
                am[mt] = reinterpret_cast<const uint4*>(ws + 2048)[aidx];
            }
            #pragma unroll
            for (int nt = 0; nt < 4; nt++) {
                int bidx = (ks * 16 + ng * 4 + nt) * 32 + lane;
                uint2 bh = xf[bidx];
                uint2 bm = xf[1024 + bidx];
                #pragma unroll
                for (int mt = 0; mt < 4; mt++) {
                    mma_bf16(c[mt][nt], ah[mt], bh);
                    mma_bf16(c[mt][nt], ah[mt], bm);
                    mma_bf16(c[mt][nt], am[mt], bh);
                }
            }
        }
    }

    // epilogue 1: bias + gelu -> gmem
    #pragma unroll
    for (int mt = 0; mt < 4; mt++) {
        int col0 = (mg * 4 + mt) * 16 + gi;
        float bb0 = B1[col0];
        float bb8 = B1[col0 + 8];
        #pragma unroll
        for (int nt = 0; nt < 4; nt++) {
            int rowx = row0 + (ng * 4 + nt) * 8 + 2 * tg;
            if (rowx < nrows) {
                Y[(size_t)rowx * 128 + col0]     = gelu_f(c[mt][nt][0] + bb0);
                Y[(size_t)rowx * 128 + col0 + 8] = gelu_f(c[mt][nt][2] + bb8);
            }
            if (rowx + 1 < nrows) {
                Y[(size_t)(rowx + 1) * 128 + col0]     = gelu_f(c[mt][nt][1] + bb0);
                Y[(size_t)(rowx + 1) * 128 + col0 + 8] = gelu_f(c[mt][nt][3] + bb8);
            }
        }
    }
}

// ---------------- launch ----------------
extern "C" void kernel_launch(void* const* d_in, const int* in_sizes, int n_in,
                              void* d_out, int out_size) {
    const float* node_repr = (const float*)d_in[0];
    const int*   edges     = (const int*)d_in[1];
    const float* edge_w    = (const float*)d_in[2];

    const float* p0g = (const float*)d_in[3];  const float* p0b = (const float*)d_in[4];
    const float* p0m = (const float*)d_in[5];  const float* p0v = (const float*)d_in[6];
    const float* p0W = (const float*)d_in[7];  const float* p0bias = (const float*)d_in[8];
    const float* p1g = (const float*)d_in[9];  const float* p1b = (const float*)d_in[10];
    const float* p1m = (const float*)d_in[11]; const float* p1v = (const float*)d_in[12];
    const float* p1W = (const float*)d_in[13]; const float* p1bias = (const float*)d_in[14];
    const float* u0g = (const float*)d_in[15]; const float* u0b = (const float*)d_in[16];
    const float* u0m = (const float*)d_in[17]; const float* u0v = (const float*)d_in[18];
    const float* u0W = (const float*)d_in[19]; const float* u0bias = (const float*)d_in[20];
    const float* u1g = (const float*)d_in[21]; const float* u1b = (const float*)d_in[22];
    const float* u1m = (const float*)d_in[23]; const float* u1v = (const float*)d_in[24];
    const float* u1W = (const float*)d_in[25]; const float* u1bias = (const float*)d_in[26];

    uint32_t* pWfrag;
    float *pbp0, *pbp1, *pbu0, *pbu1, *pPrep;
    cudaGetSymbolAddress((void**)&pWfrag, g_Wfrag);
    cudaGetSymbolAddress((void**)&pbp0, g_bp0);
    cudaGetSymbolAddress((void**)&pbp1, g_bp1);
    cudaGetSymbolAddress((void**)&pbu0, g_bu0);
    cudaGetSymbolAddress((void**)&pbu1, g_bu1);
    cudaGetSymbolAddress((void**)&pPrep, g_prep);

    const int smemB = (4096 + 4096 + 128 * YS_LD) * 4;   // 100352 B -> 2 blocks/SM
    cudaFuncSetAttribute(gemm_fused<4, false>, cudaFuncAttributeMaxDynamicSharedMemorySize, smemB);
    cudaFuncSetAttribute(gemm_fused<8, true>,  cudaFuncAttributeMaxDynamicSharedMemorySize, smemB);

    // 1) fold BN + bf16 hi/mid split, fold biases
    fold_frag<<<40, 256>>>(p0W, p0g, p0v,
                           p1W, p1g, p1v,
                           u0W, u0g, u0v,
                           u1W, u1g, u1v);
    fold_b_all<<<4, 128>>>(p0g, p0b, p0m, p0v, p0W, p0bias, pbp0,
                           p1g, p1b, p1m, p1v, p1W, p1bias, pbp1,
                           u0g, u0b, u0m, u0v, u0W, u0bias, pbu0,
                           u1g, u1b, u1m, u1v, u1W, u1bias, pbu1);
    zero_cnt<<<(NPAD + 255) / 256, 256>>>();

    const int gblocks = (NN + 127) / 128;  // 391
    // launch index 3 -> ncu capture shows the fused prep GEMM
    // 2) fused prep FFN per NODE (writes g_prep directly)
    gemm_fused<4, false><<<gblocks, 256, smemB>>>(node_repr, pWfrag, pbp0,
                                                  pWfrag + 4 * 4096, pbp1, pPrep, NN);

    // 3) CSR build + gather (writes pre-divided mean into g_agg)
    hist_kernel<<<(EE / 4 + 255) / 256, 256>>>(edges);
    scan_block<<<196, 256>>>();
    scan_tops<<<1, 256>>>(196);
    scan_finalize<<<196, 256>>>();
    fill_kernel<<<(EE / 4 + 255) / 256, 256>>>(edges, edge_w);
    gather_kernel<<<(NN + 7) / 8, 256>>>();

    // 4) fused update FFN: concat(node_repr, agg_mean) -> H -> H (writes d_out)
    gemm_fused<8, true><<<gblocks, 256, smemB>>>(node_repr, pWfrag + 8 * 4096, pbu0,
                                                 pWfrag + 16 * 4096, pbu1, (float*)d_out, NN);
}